// round 5
// baseline (speedup 1.0000x reference)
#include <cuda_runtime.h>
#include <math.h>

#define BB 256
#define HH 256
#define NLY 6
#define SS 128
#define G3 768
#define GRID 148

struct Ptrs {
  const float *x, *Wih0, *Wih, *Whh, *bih, *bhh, *h0;
  const float *aW1, *aW2, *aW3, *aW4;
  const float *sdW1,*sdb1,*sdW2,*sdb2,*sdW3,*sdb3,*sdW4,*sdb4;
  const float *odW1,*odb1,*odW2,*odb2,*odW3,*odb3,*odW4,*odb4;
  float* out;
};

// scratch (device globals -- no allocation allowed)
__device__ __align__(16) float g_h[2][NLY][BB][HH];
__device__ __align__(16) float g_hpre[NLY][BB][HH];
__device__ __align__(16) float g_sh[NLY][BB][HH];
__device__ __align__(16) float g_Gi[NLY][BB][G3];
__device__ __align__(16) float g_Gh[NLY][BB][G3];
__device__ __align__(16) float g_A3[NLY][BB][512];
// fused-attn precompute
__device__ __align__(16) float g_W2dT[NLY][512][512];
__device__ __align__(16) float g_W3d[NLY][512][512];
__device__ __align__(16) float g_W1T[NLY][256][256];
__device__ __align__(16) float g_Md[NLY][512][512];
__device__ __align__(16) float g_P[NLY][512][512];

// grid barrier state
__device__ unsigned g_bar_count = 0;
__device__ volatile unsigned g_bar_gen = 0;

#define YSEQ_OFF 8388608ul
#define YONE_OFF 9437184ul

typedef unsigned long long u64;

__device__ __forceinline__ u64 dup2(float a) {
  u64 d; unsigned ai = __float_as_uint(a);
  asm("mov.b64 %0, {%1, %1};" : "=l"(d) : "r"(ai));
  return d;
}
__device__ __forceinline__ void fma2(u64& acc, u64 a, u64 b) {
  asm("fma.rn.f32x2 %0, %1, %2, %0;" : "+l"(acc) : "l"(a), "l"(b));
}
__device__ __forceinline__ void unpack2(u64 v, float& lo, float& hi) {
  unsigned l_, h_;
  asm("mov.b64 {%0, %1}, %2;" : "=r"(l_), "=r"(h_) : "l"(v));
  lo = __uint_as_float(l_); hi = __uint_as_float(h_);
}

__device__ __forceinline__ void grid_barrier() {
  __syncthreads();
  if (threadIdx.x == 0) {
    __threadfence();
    unsigned old = g_bar_gen;
    if (atomicAdd(&g_bar_count, 1u) == GRID - 1) {
      g_bar_count = 0;
      __threadfence();
      g_bar_gen = old + 1;
    } else {
      while (g_bar_gen == old) { }
    }
    __threadfence();
  }
  __syncthreads();
}

// ---------------------------------------------------------------------------
// GEMM core: TM x 128 output tile, 256 threads, TK=8, double-buffered smem.
// N-paired f32x2 accumulators: acc[i][j] = cols (n0+tx*8+2j, +1), row ty*IM+i.
// A concat: col c<256 from A0, c>=256 from A1 (both stride lda; lda==0 ->
// broadcast row). W row-major [128 rows of this n-tile, K], stride ldb.
// ---------------------------------------------------------------------------
template<int TM>
__device__ __forceinline__ void gemm_core(
    const float* __restrict__ A0, const float* __restrict__ A1, int lda,
    const float* __restrict__ W, int ldb, int K,
    u64 acc[TM/16][4], float* As, float* Bs)
{
  constexpr int IM = TM / 16;
  const int t  = threadIdx.x;
  const int tx = t & 15, ty = t >> 4;
  int ar, ak;
  if (TM == 64) { ar = t >> 2; ak = (t & 3) * 2; }
  else          { ar = t >> 3; ak = (t & 7); }
  const int br = t >> 1, bo = (t & 1) * 4;

  float a0v, a1v; float4 rb;
  auto loadT = [&](int k0) {
    int c = k0 + ak;
    const float* base = (c < 256) ? (A0 + c) : (A1 + (c - 256));
    const float* pa = base + (size_t)ar * lda;
    if (TM == 64) { float2 v = *(const float2*)pa; a0v = v.x; a1v = v.y; }
    else          { a0v = *pa; }
    rb = *(const float4*)(W + (size_t)br * ldb + k0 + bo);
  };
  auto storeT = [&](int buf) {
    float* as = As + buf * (8 * TM);
    float* bs = Bs + buf * 1024;
    if (TM == 64) { as[ak*TM + ar] = a0v; as[(ak+1)*TM + ar] = a1v; }
    else          { as[ak*TM + ar] = a0v; }
    bs[(bo+0)*128 + br] = rb.x; bs[(bo+1)*128 + br] = rb.y;
    bs[(bo+2)*128 + br] = rb.z; bs[(bo+3)*128 + br] = rb.w;
  };
  auto compute = [&](int buf) {
    const float* as = As + buf * (8 * TM) + ty * IM;
    const float* bs = Bs + buf * 1024 + tx * 8;
#pragma unroll
    for (int kk = 0; kk < 8; kk++) {
      float av[IM];
      if (TM == 64) {
        float4 a4v = *(const float4*)(as + kk * TM);
        av[0]=a4v.x; av[1]=a4v.y; av[2]=a4v.z; av[3]=a4v.w;
      } else {
        float2 a2v = *(const float2*)(as + kk * TM);
        av[0]=a2v.x; av[1]=a2v.y;
      }
      ulonglong2 b0 = *(const ulonglong2*)(bs + kk * 128);
      ulonglong2 b1 = *(const ulonglong2*)(bs + kk * 128 + 4);
      u64 bp[4] = {b0.x, b0.y, b1.x, b1.y};
      u64 ad[IM];
#pragma unroll
      for (int i = 0; i < IM; i++) ad[i] = dup2(av[i]);
#pragma unroll
      for (int i = 0; i < IM; i++)
#pragma unroll
        for (int j = 0; j < 4; j++) fma2(acc[i][j], ad[i], bp[j]);
    }
  };

  const int nb = K >> 3;
  loadT(0); storeT(0); __syncthreads();
  for (int kb = 1; kb < nb; kb++) {
    loadT(kb << 3);
    compute((kb - 1) & 1);
    storeT(kb & 1);
    __syncthreads();
  }
  compute((nb - 1) & 1);
  __syncthreads();          // smem reused by next tile in the same phase
}

template<int IM>
__device__ __forceinline__ void unp(u64 acc[IM][4], float v[IM][8]) {
#pragma unroll
  for (int i = 0; i < IM; i++)
#pragma unroll
    for (int j = 0; j < 4; j++)
      unpack2(acc[i][j], v[i][2*j], v[i][2*j+1]);
}

// ---------------------------------------------------------------------------
// Prep kernels (one-time per launch): fold SortAttn shuffles+W1,W2,W3 into P.
// ---------------------------------------------------------------------------
__global__ void prep_zero() {
  int i = blockIdx.x * 256 + threadIdx.x;
  if (i < NLY * 512 * 512) {
    ((float*)g_W2dT)[i] = 0.f;
    ((float*)g_W3d)[i] = 0.f;
  }
}

__global__ void prep_scatter(Ptrs P) {
  int i = blockIdx.x * 256 + threadIdx.x;
  if (i >= NLY * 4 * 128 * 128) return;
  int l = i >> 16; int r = i & 65535;
  int g = r >> 14; int j = (r >> 7) & 127; int m = r & 127;
  int v = g * 128 + m;
  int c = ((v & 3) << 7) + (v >> 2);
  g_W2dT[l][c][g*128 + j] = P.aW2[((size_t)l*128 + j)*128 + m];
  g_W3d[l][g*128 + j][c]  = P.aW3[((size_t)l*128 + j)*128 + m];
}

__global__ void prep_w1t(Ptrs P) {
  int i = blockIdx.x * 256 + threadIdx.x;
  if (i >= NLY * 256 * 256) return;
  int l = i >> 16; int r = i & 65535; int c1 = r >> 8; int k = r & 255;
  g_W1T[l][k][c1] = P.aW1[(size_t)l*65536 + (size_t)c1*256 + k];
}

__global__ void __launch_bounds__(256) prep_md() {
  __shared__ __align__(16) float As[2*8*64], Bs[2*8*128];
  int l = blockIdx.y;
  int m0 = (blockIdx.x & 7) << 6, n0 = (blockIdx.x >> 3) << 7;
  const float* A0 = &g_W3d[l][m0][0];
  const float* W  = &g_W2dT[l][n0][0];
  u64 acc[4][4] = {};
  gemm_core<64>(A0, A0 + 256, 512, W, 512, 512, acc, As, Bs);
  float v[4][8]; unp<4>(acc, v);
  int tx = threadIdx.x & 15, ty = threadIdx.x >> 4;
#pragma unroll
  for (int r = 0; r < 4; r++) {
    int m = m0 + ty*4 + r;
    float* po = &g_Md[l][m][n0 + tx*8];
    *(float4*)(po)     = make_float4(v[r][0], v[r][1], v[r][2], v[r][3]);
    *(float4*)(po + 4) = make_float4(v[r][4], v[r][5], v[r][6], v[r][7]);
  }
}

__global__ void __launch_bounds__(256) prep_p() {
  __shared__ __align__(16) float As[2*8*64], Bs[2*8*128];
  int l = blockIdx.y;
  int m0 = (blockIdx.x & 7) << 6;
  int nt = blockIdx.x >> 3;              // 0..3
  int half = nt >> 1;
  const float* A0 = &g_Md[l][m0][half * 256];
  const float* W  = &g_W1T[l][(nt & 1) * 128][0];
  u64 acc[4][4] = {};
  gemm_core<64>(A0, A0, 512, W, 256, 256, acc, As, Bs);
  float v[4][8]; unp<4>(acc, v);
  int tx = threadIdx.x & 15, ty = threadIdx.x >> 4;
#pragma unroll
  for (int r = 0; r < 4; r++) {
    int m = m0 + ty*4 + r;
    float* po = &g_P[l][m][nt*128 + tx*8];
    *(float4*)(po)     = make_float4(v[r][0], v[r][1], v[r][2], v[r][3]);
    *(float4*)(po + 4) = make_float4(v[r][4], v[r][5], v[r][6], v[r][7]);
  }
}

// ---------------------------------------------------------------------------
// Phase tile bodies (called from the persistent kernel)
// ---------------------------------------------------------------------------
__device__ __forceinline__ void tile_stage1(const Ptrs& P, int w, int l, int i,
                                            int pp, float* As, float* Bs) {
  int t = w - l;
  int which = (i >= 24); i -= which * 24;
  int m0 = (i & 3) << 6, n0 = (i >> 2) << 7;
  const float *A0, *W; int lda, K; float* out;
  if (!which) {
    if (l == 0) { A0 = P.x + (size_t)t*128 + (size_t)m0*16384; lda = 16384; K = 128;
                  W = P.Wih0 + (size_t)n0 * 128; }
    else        { A0 = &g_h[pp][l-1][m0][0]; lda = HH; K = HH;
                  W = P.Wih + ((size_t)(l-1)*G3 + n0) * HH; }
    out = &g_Gi[l][0][0];
  } else {
    if (t == 0) { A0 = P.h0 + l*HH; lda = 0; }
    else        { A0 = &g_h[pp][l][m0][0]; lda = HH; }
    K = HH; W = P.Whh + ((size_t)l*G3 + n0) * HH;
    out = &g_Gh[l][0][0];
  }
  u64 acc[4][4] = {};
  gemm_core<64>(A0, A0, lda, W, K, K, acc, As, Bs);
  float v[4][8]; unp<4>(acc, v);
  int tx = threadIdx.x & 15, ty = threadIdx.x >> 4;
#pragma unroll
  for (int r = 0; r < 4; r++) {
    int m = m0 + ty*4 + r;
    float* po = out + (size_t)m * G3 + n0 + tx*8;
    *(float4*)(po)     = make_float4(v[r][0], v[r][1], v[r][2], v[r][3]);
    *(float4*)(po + 4) = make_float4(v[r][4], v[r][5], v[r][6], v[r][7]);
  }
}

__device__ __forceinline__ void tile_gatesort(const Ptrs& P, int w, int l,
                                              int blk, int pp, float* vbuf) {
  int t = w - l;
  int warp = threadIdx.x >> 5, lane = threadIdx.x & 31;
  int b = blk * 8 + warp;
  float* v = vbuf + warp * 256;
  const float* bi = P.bih + l * G3;
  const float* bh = P.bhh + l * G3;
#pragma unroll
  for (int q = 0; q < 8; q++) {
    int j = lane + (q << 5);
    float gi0 = g_Gi[l][b][j]      + bi[j];
    float gi1 = g_Gi[l][b][j+256]  + bi[j+256];
    float gi2 = g_Gi[l][b][j+512]  + bi[j+512];
    float gh0 = g_Gh[l][b][j]      + bh[j];
    float gh1 = g_Gh[l][b][j+256]  + bh[j+256];
    float gh2 = g_Gh[l][b][j+512]  + bh[j+512];
    float r = 1.f / (1.f + expf(-(gi0 + gh0)));
    float z = 1.f / (1.f + expf(-(gi1 + gh1)));
    float n = tanhf(gi2 + r * gh2);
    float hp = (t == 0) ? P.h0[l * HH + j] : g_h[pp][l][b][j];
    float hv = (1.f - z) * n + z * hp;
    g_hpre[l][b][j] = hv;
    v[j] = hv;
  }
  __syncwarp();
  for (int k = 2; k <= 256; k <<= 1) {
    for (int jj = k >> 1; jj > 0; jj >>= 1) {
#pragma unroll
      for (int q = 0; q < 8; q++) {
        int idx = lane + (q << 5);
        int ixj = idx ^ jj;
        if (ixj > idx) {
          float a = v[idx], c = v[ixj];
          bool up = ((idx & k) == 0);
          if ((a > c) == up) { v[idx] = c; v[ixj] = a; }
        }
      }
      __syncwarp();
    }
  }
#pragma unroll
  for (int q = 0; q < 8; q++) {
    int j = lane + (q << 5);
    g_sh[l][b][j] = v[j];
  }
}

__device__ __forceinline__ void tile_attn(int l, int i, float* As, float* Bs) {
  int m0 = (i & 3) << 6, n0 = (i >> 2) << 7;
  const float* A0 = &g_hpre[l][m0][0];
  const float* A1 = &g_sh[l][m0][0];
  const float* W  = &g_P[l][n0][0];
  u64 acc[4][4] = {};
  gemm_core<64>(A0, A1, 256, W, 512, 512, acc, As, Bs);
  float v[4][8]; unp<4>(acc, v);
  int tx = threadIdx.x & 15, ty = threadIdx.x >> 4;
#pragma unroll
  for (int r = 0; r < 4; r++) {
    int m = m0 + ty*4 + r;
#pragma unroll
    for (int q = 0; q < 8; q++) v[r][q] = fmaxf(v[r][q], 0.f);
    float* po = &g_A3[l][m][n0 + tx*8];
    *(float4*)(po)     = make_float4(v[r][0], v[r][1], v[r][2], v[r][3]);
    *(float4*)(po + 4) = make_float4(v[r][4], v[r][5], v[r][6], v[r][7]);
  }
}

__device__ __forceinline__ void tile_a4(const Ptrs& P, int w, int l, int i,
                                        int p, float* As, float* Bs) {
  int t = w - l;
  int m0 = (i & 7) << 5, n0 = (i >> 3) << 7;
  const float* A0 = &g_A3[l][m0][0];
  const float* W  = P.aW4 + ((size_t)l*256 + n0) * 512;
  u64 acc[2][4] = {};
  gemm_core<32>(A0, A0 + 256, 512, W, 512, 512, acc, As, Bs);
  float v[2][8]; unp<2>(acc, v);
  int tx = threadIdx.x & 15, ty = threadIdx.x >> 4;
#pragma unroll
  for (int r = 0; r < 2; r++) {
    int m = m0 + ty*2 + r;
    int n = n0 + tx*8;
#pragma unroll
    for (int q = 0; q < 8; q++) {
      float hv = g_hpre[l][m][n+q] * (1.f / (1.f + expf(-v[r][q])));
      g_h[p][l][m][n+q] = hv;
      if (l == NLY - 1)
        P.out[(size_t)m * 32768 + (size_t)t * 256 + n + q] = hv;
    }
  }
}

// ---------------------------------------------------------------------------
// The persistent kernel: 148 CTAs, whole recurrence, 4 phases per wavefront.
// ---------------------------------------------------------------------------
__global__ void __launch_bounds__(256) persist_k(Ptrs P) {
  __shared__ __align__(16) float smem[3072];   // As[1024] | Bs[2048]; gatesort uses [0..2047]
  float* As = smem;
  float* Bs = smem + 1024;
  const int bid = blockIdx.x;

  for (int w = 0; w < SS + NLY - 1; w++) {
    int lmin = w - (SS - 1); if (lmin < 0) lmin = 0;
    int lmax = (w < NLY - 1) ? w : NLY - 1;
    int nA = lmax - lmin + 1;
    int pp = (w + 1) & 1;
    int p  = w & 1;

    for (int idx = bid; idx < nA * 48; idx += GRID)
      tile_stage1(P, w, lmin + idx / 48, idx % 48, pp, As, Bs);
    grid_barrier();

    for (int idx = bid; idx < nA * 32; idx += GRID)
      tile_gatesort(P, w, lmin + idx / 32, idx % 32, pp, smem);
    grid_barrier();

    for (int idx = bid; idx < nA * 16; idx += GRID)
      tile_attn(lmin + idx / 16, idx % 16, As, Bs);
    grid_barrier();

    for (int idx = bid; idx < nA * 16; idx += GRID)
      tile_a4(P, w, lmin + idx / 16, idx % 16, p, As, Bs);
    grid_barrier();
  }
}

// ---------------------------------------------------------------------------
__global__ void seqdec_kernel(Ptrs P) {
  int idx = blockIdx.x * blockDim.x + threadIdx.x;
  int b = idx >> 7, s = idx & 127;
  const float* e = P.out + (size_t)b * 32768 + (size_t)s * 256;
  float a1[8][4], a2[8][4], a3[8][4];
#pragma unroll
  for (int g = 0; g < 8; g++)
#pragma unroll
    for (int o = 0; o < 4; o++) {
      float sum = P.sdb1[o];
#pragma unroll
      for (int m = 0; m < 32; m++) sum += e[g*32+m] * P.sdW1[o*32+m];
      a1[g][o] = sum;
    }
#pragma unroll
  for (int i = 0; i < 8; i++)
#pragma unroll
    for (int o = 0; o < 4; o++) {
      float sum = P.sdb2[o];
#pragma unroll
      for (int j = 0; j < 4; j++) {
        int f = i*4 + j;
        sum += a1[f & 7][f >> 3] * P.sdW2[o*4+j];
      }
      a2[i][o] = sum;
    }
#pragma unroll
  for (int i = 0; i < 8; i++)
#pragma unroll
    for (int o = 0; o < 4; o++) {
      float sum = P.sdb3[o];
#pragma unroll
      for (int j = 0; j < 4; j++) {
        int f = i*4 + j;
        sum += a2[f & 7][f >> 3] * P.sdW3[o*4+j];
      }
      a3[i][o] = sum;
    }
#pragma unroll
  for (int o = 0; o < 4; o++)
#pragma unroll
    for (int wv = 0; wv < 8; wv++) {
      float sum = P.sdb4[wv];
#pragma unroll
      for (int g = 0; g < 8; g++) {
        int f = o*8 + g;
        sum += a3[f >> 2][f & 3] * P.sdW4[wv*8+g];
      }
      P.out[YSEQ_OFF + (size_t)b * 4096 + (size_t)(s*8 + wv) * 4 + o] = sum;
    }
}

// ---------------------------------------------------------------------------
__global__ void onedec_kernel(Ptrs P) {
  int b = blockIdx.x;
  __shared__ float acc[10][4];
  int tid = threadIdx.x;
  if (tid < 10) {
    int s = 118 + tid;
    const float* e = P.out + (size_t)b * 32768 + (size_t)s * 256;
    float o1[8][4], o2[8][4], o3[8][4];
#pragma unroll
    for (int g = 0; g < 8; g++)
#pragma unroll
      for (int o = 0; o < 4; o++) {
        float sum = P.odb1[o];
#pragma unroll
        for (int m = 0; m < 32; m++) sum += e[g*32+m] * P.odW1[o*32+m];
        o1[g][o] = sum;
      }
#pragma unroll
    for (int i = 0; i < 8; i++)
#pragma unroll
      for (int o = 0; o < 4; o++) {
        float sum = P.odb2[o];
#pragma unroll
        for (int j = 0; j < 4; j++) {
          int f = i*4 + j;
          sum += o1[f & 7][f >> 3] * P.odW2[o*4+j];
        }
        o2[i][o] = sum;
      }
#pragma unroll
    for (int i = 0; i < 8; i++)
#pragma unroll
      for (int o = 0; o < 4; o++) {
        float sum = P.odb3[o];
#pragma unroll
        for (int j = 0; j < 4; j++) {
          int f = i*4 + j;
          sum += o2[f & 7][f >> 3] * P.odW3[o*4+j];
        }
        o3[i][o] = fmaxf(sum, 0.f);
      }
#pragma unroll
    for (int c = 0; c < 4; c++) {
      float sum = P.odb4[c];
#pragma unroll
      for (int f = 0; f < 32; f++) sum += o3[f >> 2][f & 3] * P.odW4[c*32+f];
      acc[tid][c] = 1.f / (1.f + expf(-sum));
    }
  }
  __syncthreads();
  if (tid < 4) {
    float s = 0.f;
#pragma unroll
    for (int i = 0; i < 10; i++) s += acc[i][tid];
    P.out[YONE_OFF + (size_t)b * 4 + tid] = s * 0.1f;
  }
}

// ---------------------------------------------------------------------------
extern "C" void kernel_launch(void* const* d_in, const int* in_sizes, int n_in,
                              void* d_out, int out_size) {
  (void)in_sizes; (void)n_in; (void)out_size;
  Ptrs P;
  P.x    = (const float*)d_in[0];
  P.Wih0 = (const float*)d_in[1];
  P.Wih  = (const float*)d_in[2];
  P.Whh  = (const float*)d_in[3];
  P.bih  = (const float*)d_in[4];
  P.bhh  = (const float*)d_in[5];
  P.h0   = (const float*)d_in[6];
  P.aW1  = (const float*)d_in[7];
  P.aW2  = (const float*)d_in[8];
  P.aW3  = (const float*)d_in[9];
  P.aW4  = (const float*)d_in[10];
  P.sdW1 = (const float*)d_in[11];
  P.sdb1 = (const float*)d_in[12];
  P.sdW2 = (const float*)d_in[13];
  P.sdb2 = (const float*)d_in[14];
  P.sdW3 = (const float*)d_in[15];
  P.sdb3 = (const float*)d_in[16];
  P.sdW4 = (const float*)d_in[17];
  P.sdb4 = (const float*)d_in[18];
  P.odW1 = (const float*)d_in[19];
  P.odb1 = (const float*)d_in[20];
  P.odW2 = (const float*)d_in[21];
  P.odb2 = (const float*)d_in[22];
  P.odW3 = (const float*)d_in[23];
  P.odb3 = (const float*)d_in[24];
  P.odW4 = (const float*)d_in[25];
  P.odb4 = (const float*)d_in[26];
  P.out  = (float*)d_out;

  // one-time fold of SortAttn (shuffle,W1,W2,W3) into dense P per layer
  prep_zero<<<6144, 256>>>();
  prep_scatter<<<1536, 256>>>(P);
  prep_w1t<<<1536, 256>>>(P);
  prep_md<<<dim3(32, NLY), 256>>>();
  prep_p<<<dim3(32, NLY), 256>>>();

  // entire recurrence in one persistent kernel
  persist_k<<<GRID, 256>>>(P);

  seqdec_kernel<<<128, 256>>>(P);
  onedec_kernel<<<256, 32>>>(P);
}

// round 6
// speedup vs baseline: 1.3078x; 1.3078x over previous
#include <cuda_runtime.h>
#include <math.h>

#define BB 256
#define HH 256
#define NLY 6
#define SS 128
#define G3 768

struct Ptrs {
  const float *x, *Wih0, *Wih, *Whh, *bih, *bhh, *h0;
  const float *aW1, *aW2, *aW3, *aW4;
  const float *sdW1,*sdb1,*sdW2,*sdb2,*sdW3,*sdb3,*sdW4,*sdb4;
  const float *odW1,*odb1,*odW2,*odb2,*odW3,*odb3,*odW4,*odb4;
  float* out;
};

// scratch (device globals -- no allocation allowed)
__device__ __align__(16) float g_h[2][NLY][BB][HH];
__device__ __align__(16) float g_hpre[NLY][BB][HH];
__device__ __align__(16) float g_sh[NLY][BB][HH];
__device__ __align__(16) float g_Gi[NLY][BB][G3];
__device__ __align__(16) float g_Gh[NLY][BB][G3];
__device__ __align__(16) float g_A3[NLY][BB][512];
// fused-attn precompute
__device__ __align__(16) float g_W2dT[NLY][512][512];
__device__ __align__(16) float g_W3d[NLY][512][512];
__device__ __align__(16) float g_W1T[NLY][256][256];
__device__ __align__(16) float g_Md[NLY][512][512];
__device__ __align__(16) float g_P[NLY][512][512];

#define YSEQ_OFF 8388608ul
#define YONE_OFF 9437184ul

typedef unsigned long long u64;

__device__ __forceinline__ u64 dup2(float a) {
  u64 d; unsigned ai = __float_as_uint(a);
  asm("mov.b64 %0, {%1, %1};" : "=l"(d) : "r"(ai));
  return d;
}
__device__ __forceinline__ void fma2(u64& acc, u64 a, u64 b) {
  asm("fma.rn.f32x2 %0, %1, %2, %0;" : "+l"(acc) : "l"(a), "l"(b));
}
__device__ __forceinline__ void unpack2(u64 v, float& lo, float& hi) {
  unsigned l_, h_;
  asm("mov.b64 {%0, %1}, %2;" : "=r"(l_), "=r"(h_) : "l"(v));
  lo = __uint_as_float(l_); hi = __uint_as_float(h_);
}

// ---------------------------------------------------------------------------
// 64x64 tile, 256 threads (16x16), 4x4 per thread, TK=8, double-buffered.
// acc[r][j] (u64) = row ty*4+r, cols (tx*4+2j, tx*4+2j+1).
// A concat: col c<256 from A0, else A1+(c-256); stride lda (0 = broadcast row).
// W row-major [64 n-rows of this tile, K], stride ldb, pre-offset to n0.
// ---------------------------------------------------------------------------
__device__ __forceinline__ void gemm64(
    const float* __restrict__ A0, const float* __restrict__ A1, int lda,
    const float* __restrict__ W, int ldb, int K,
    u64 acc[4][2], float* As, float* Bs)
{
  const int t = threadIdx.x;
  const int ar = t >> 2, ak = (t & 3) << 1;
  const int tx = t & 15, ty = t >> 4;
  float2 ra, rb;
  auto loadT = [&](int k0) {
    int c = k0 + ak;
    const float* base = (c < 256) ? (A0 + c) : (A1 + (c - 256));
    ra = *(const float2*)(base + (size_t)ar * lda);
    rb = *(const float2*)(W + (size_t)ar * ldb + k0 + ak);
  };
  auto storeT = [&](int buf) {
    float* as = As + buf * 512;
    float* bs = Bs + buf * 512;
    as[ak*64 + ar] = ra.x; as[(ak+1)*64 + ar] = ra.y;
    bs[ak*64 + ar] = rb.x; bs[(ak+1)*64 + ar] = rb.y;
  };
  auto compute = [&](int buf) {
    const float* as = As + buf * 512 + ty * 4;
    const float* bs = Bs + buf * 512 + tx * 4;
#pragma unroll
    for (int kk = 0; kk < 8; kk++) {
      float4 a4v = *(const float4*)(as + kk * 64);
      ulonglong2 b2 = *(const ulonglong2*)(bs + kk * 64);
      u64 ad;
      ad = dup2(a4v.x); fma2(acc[0][0], ad, b2.x); fma2(acc[0][1], ad, b2.y);
      ad = dup2(a4v.y); fma2(acc[1][0], ad, b2.x); fma2(acc[1][1], ad, b2.y);
      ad = dup2(a4v.z); fma2(acc[2][0], ad, b2.x); fma2(acc[2][1], ad, b2.y);
      ad = dup2(a4v.w); fma2(acc[3][0], ad, b2.x); fma2(acc[3][1], ad, b2.y);
    }
  };
  const int nb = K >> 3;
  loadT(0); storeT(0); __syncthreads();
  for (int kb = 1; kb < nb; kb++) {
    loadT(kb << 3);
    compute((kb - 1) & 1);
    storeT(kb & 1);
    __syncthreads();
  }
  compute((nb - 1) & 1);
}

// ---------------------------------------------------------------------------
// 32x64 tile, 256 threads (16x16), 2x4 per thread, TK=8, double-buffered.
// ---------------------------------------------------------------------------
__device__ __forceinline__ void gemm32(
    const float* __restrict__ A0, const float* __restrict__ A1, int lda,
    const float* __restrict__ W, int ldb, int K,
    u64 acc[2][2], float* As, float* Bs)
{
  const int t = threadIdx.x;
  const int ar = t >> 3, ak = t & 7;             // A: 32 rows x 8k, 1 float
  const int br = t >> 2, bk = (t & 3) << 1;      // B: 64 rows x 8k, float2
  const int tx = t & 15, ty = t >> 4;
  float ra; float2 rb;
  auto loadT = [&](int k0) {
    int c = k0 + ak;
    const float* base = (c < 256) ? (A0 + c) : (A1 + (c - 256));
    ra = *(base + (size_t)ar * lda);
    rb = *(const float2*)(W + (size_t)br * ldb + k0 + bk);
  };
  auto storeT = [&](int buf) {
    float* as = As + buf * 256;
    float* bs = Bs + buf * 512;
    as[ak*32 + ar] = ra;
    bs[bk*64 + br] = rb.x; bs[(bk+1)*64 + br] = rb.y;
  };
  auto compute = [&](int buf) {
    const float* as = As + buf * 256 + ty * 2;
    const float* bs = Bs + buf * 512 + tx * 4;
#pragma unroll
    for (int kk = 0; kk < 8; kk++) {
      float2 a2v = *(const float2*)(as + kk * 32);
      ulonglong2 b2 = *(const ulonglong2*)(bs + kk * 64);
      u64 ad;
      ad = dup2(a2v.x); fma2(acc[0][0], ad, b2.x); fma2(acc[0][1], ad, b2.y);
      ad = dup2(a2v.y); fma2(acc[1][0], ad, b2.x); fma2(acc[1][1], ad, b2.y);
    }
  };
  const int nb = K >> 3;
  loadT(0); storeT(0); __syncthreads();
  for (int kb = 1; kb < nb; kb++) {
    loadT(kb << 3);
    compute((kb - 1) & 1);
    storeT(kb & 1);
    __syncthreads();
  }
  compute((nb - 1) & 1);
}

// ---------------------------------------------------------------------------
// Prep: fold SortAttn shuffles + W1/W2/W3 into dense P (one-time per launch).
// ---------------------------------------------------------------------------
__global__ void prep_zero() {
  int i = blockIdx.x * 256 + threadIdx.x;
  if (i < NLY * 512 * 512) {
    ((float*)g_W2dT)[i] = 0.f;
    ((float*)g_W3d)[i] = 0.f;
  }
}

__global__ void prep_scatter(Ptrs P) {
  int i = blockIdx.x * 256 + threadIdx.x;
  if (i >= NLY * 4 * 128 * 128) return;
  int l = i >> 16; int r = i & 65535;
  int g = r >> 14; int j = (r >> 7) & 127; int m = r & 127;
  int v = g * 128 + m;
  int c = ((v & 3) << 7) + (v >> 2);
  g_W2dT[l][c][g*128 + j] = P.aW2[((size_t)l*128 + j)*128 + m];
  g_W3d[l][g*128 + j][c]  = P.aW3[((size_t)l*128 + j)*128 + m];
}

__global__ void prep_w1t(Ptrs P) {
  int i = blockIdx.x * 256 + threadIdx.x;
  if (i >= NLY * 256 * 256) return;
  int l = i >> 16; int r = i & 65535; int c1 = r >> 8; int k = r & 255;
  g_W1T[l][k][c1] = P.aW1[(size_t)l*65536 + (size_t)c1*256 + k];
}

__global__ void __launch_bounds__(256, 4) prep_md() {
  __shared__ __align__(16) float As[1024], Bs[1024];
  int l = blockIdx.y;
  int i = blockIdx.x;                    // 0..63
  int m0 = (i & 7) << 6, n0 = (i >> 3) << 6;
  const float* A0 = &g_W3d[l][m0][0];
  const float* W  = &g_W2dT[l][n0][0];
  u64 acc[4][2] = {};
  gemm64(A0, A0 + 256, 512, W, 512, 512, acc, As, Bs);
  int tx = threadIdx.x & 15, ty = threadIdx.x >> 4;
#pragma unroll
  for (int r = 0; r < 4; r++) {
    float v0,v1,v2,v3;
    unpack2(acc[r][0], v0, v1); unpack2(acc[r][1], v2, v3);
    *(float4*)(&g_Md[l][m0 + ty*4 + r][n0 + tx*4]) = make_float4(v0,v1,v2,v3);
  }
}

__global__ void __launch_bounds__(256, 4) prep_p() {
  __shared__ __align__(16) float As[1024], Bs[1024];
  int l = blockIdx.y;
  int i = blockIdx.x;                    // 0..63
  int m0 = (i & 7) << 6;
  int nt = i >> 3;                       // 0..7 (64-wide out col tiles)
  int half = nt >> 2;
  const float* A0 = &g_Md[l][m0][half * 256];
  const float* W  = &g_W1T[l][(nt & 3) * 64][0];
  u64 acc[4][2] = {};
  gemm64(A0, A0, 512, W, 256, 256, acc, As, Bs);
  int tx = threadIdx.x & 15, ty = threadIdx.x >> 4;
#pragma unroll
  for (int r = 0; r < 4; r++) {
    float v0,v1,v2,v3;
    unpack2(acc[r][0], v0, v1); unpack2(acc[r][1], v2, v3);
    *(float4*)(&g_P[l][m0 + ty*4 + r][nt*64 + tx*4]) = make_float4(v0,v1,v2,v3);
  }
}

// ---------------------------------------------------------------------------
// Stage 1: Gi = inp @ Wih^T ; Gh = h_prev @ Whh^T.  grid(96, nA), 256 thr.
// ---------------------------------------------------------------------------
__global__ void __launch_bounds__(256, 4) stage1_k(Ptrs P, int w, int lmin, int pp) {
  __shared__ __align__(16) float As[1024], Bs[1024];
  int l = lmin + blockIdx.y, t = w - l;
  int i = blockIdx.x;                    // 0..95
  int which = (i >= 48); i -= which * 48;
  int m0 = (i & 3) << 6, n0 = (i >> 2) << 6;   // n0: 0..704
  const float *A0, *W; int lda, K; float* out;
  if (!which) {
    if (l == 0) { A0 = P.x + (size_t)t*128 + (size_t)m0*16384; lda = 16384; K = 128;
                  W = P.Wih0 + (size_t)n0 * 128; }
    else        { A0 = &g_h[pp][l-1][m0][0]; lda = HH; K = HH;
                  W = P.Wih + ((size_t)(l-1)*G3 + n0) * HH; }
    out = &g_Gi[l][0][0];
  } else {
    if (t == 0) { A0 = P.h0 + l*HH; lda = 0; }
    else        { A0 = &g_h[pp][l][m0][0]; lda = HH; }
    K = HH; W = P.Whh + ((size_t)l*G3 + n0) * HH;
    out = &g_Gh[l][0][0];
  }
  u64 acc[4][2] = {};
  gemm64(A0, A0, lda, W, K, K, acc, As, Bs);
  int tx = threadIdx.x & 15, ty = threadIdx.x >> 4;
#pragma unroll
  for (int r = 0; r < 4; r++) {
    float v0,v1,v2,v3;
    unpack2(acc[r][0], v0, v1); unpack2(acc[r][1], v2, v3);
    *(float4*)(out + (size_t)(m0 + ty*4 + r) * G3 + n0 + tx*4) = make_float4(v0,v1,v2,v3);
  }
}

// ---------------------------------------------------------------------------
// Stage 2: gates -> hpre, warp-synchronous bitonic sort -> sh. grid(32, nA)
// ---------------------------------------------------------------------------
__global__ void __launch_bounds__(256) gatesort_k(Ptrs P, int w, int lmin, int pp) {
  int l = lmin + blockIdx.y, t = w - l;
  int warp = threadIdx.x >> 5, lane = threadIdx.x & 31;
  int b = blockIdx.x * 8 + warp;
  __shared__ float vbuf[8][256];
  float* v = vbuf[warp];
  const float* bi = P.bih + l * G3;
  const float* bh = P.bhh + l * G3;
#pragma unroll
  for (int q = 0; q < 8; q++) {
    int j = lane + (q << 5);
    float gi0 = g_Gi[l][b][j]      + bi[j];
    float gi1 = g_Gi[l][b][j+256]  + bi[j+256];
    float gi2 = g_Gi[l][b][j+512]  + bi[j+512];
    float gh0 = g_Gh[l][b][j]      + bh[j];
    float gh1 = g_Gh[l][b][j+256]  + bh[j+256];
    float gh2 = g_Gh[l][b][j+512]  + bh[j+512];
    float r = 1.f / (1.f + expf(-(gi0 + gh0)));
    float z = 1.f / (1.f + expf(-(gi1 + gh1)));
    float n = tanhf(gi2 + r * gh2);
    float hp = (t == 0) ? P.h0[l * HH + j] : g_h[pp][l][b][j];
    float hv = (1.f - z) * n + z * hp;
    g_hpre[l][b][j] = hv;
    v[j] = hv;
  }
  __syncwarp();
  for (int k = 2; k <= 256; k <<= 1) {
    for (int jj = k >> 1; jj > 0; jj >>= 1) {
#pragma unroll
      for (int q = 0; q < 8; q++) {
        int idx = lane + (q << 5);
        int ixj = idx ^ jj;
        if (ixj > idx) {
          float a = v[idx], c = v[ixj];
          bool up = ((idx & k) == 0);
          if ((a > c) == up) { v[idx] = c; v[ixj] = a; }
        }
      }
      __syncwarp();
    }
  }
#pragma unroll
  for (int q = 0; q < 8; q++) {
    int j = lane + (q << 5);
    g_sh[l][b][j] = v[j];
  }
}

// ---------------------------------------------------------------------------
// Stage 3 (fused a1+a2+a3): A3 = relu([hpre | sh] @ P^T). grid(64, nA)
// ---------------------------------------------------------------------------
__global__ void __launch_bounds__(256, 4) attn_k(int lmin) {
  __shared__ __align__(16) float As[512], Bs[1024];
  int l = lmin + blockIdx.y;
  int i = blockIdx.x;                    // 0..63
  int m0 = (i & 7) << 5, n0 = (i >> 3) << 6;
  const float* A0 = &g_hpre[l][m0][0];
  const float* A1 = &g_sh[l][m0][0];
  const float* W  = &g_P[l][n0][0];
  u64 acc[2][2] = {};
  gemm32(A0, A1, 256, W, 512, 512, acc, As, Bs);
  int tx = threadIdx.x & 15, ty = threadIdx.x >> 4;
#pragma unroll
  for (int r = 0; r < 2; r++) {
    float v0,v1,v2,v3;
    unpack2(acc[r][0], v0, v1); unpack2(acc[r][1], v2, v3);
    v0 = fmaxf(v0, 0.f); v1 = fmaxf(v1, 0.f);
    v2 = fmaxf(v2, 0.f); v3 = fmaxf(v3, 0.f);
    *(float4*)(&g_A3[l][m0 + ty*2 + r][n0 + tx*4]) = make_float4(v0,v1,v2,v3);
  }
}

// ---------------------------------------------------------------------------
// Stage 4: a4 = A3 @ W4^T ; h = hpre * sigmoid(a4). grid(32, nA)
// ---------------------------------------------------------------------------
__global__ void __launch_bounds__(256, 4) a4_k(Ptrs P, int w, int lmin, int p) {
  __shared__ __align__(16) float As[512], Bs[1024];
  int l = lmin + blockIdx.y, t = w - l;
  int i = blockIdx.x;                    // 0..31
  int m0 = (i & 7) << 5, n0 = (i >> 3) << 6;
  const float* A0 = &g_A3[l][m0][0];
  const float* W  = P.aW4 + ((size_t)l*256 + n0) * 512;
  u64 acc[2][2] = {};
  gemm32(A0, A0 + 256, 512, W, 512, 512, acc, As, Bs);
  int tx = threadIdx.x & 15, ty = threadIdx.x >> 4;
#pragma unroll
  for (int r = 0; r < 2; r++) {
    int m = m0 + ty*2 + r;
    int n = n0 + tx*4;
    float v[4];
    unpack2(acc[r][0], v[0], v[1]); unpack2(acc[r][1], v[2], v[3]);
#pragma unroll
    for (int q = 0; q < 4; q++) {
      float hv = g_hpre[l][m][n+q] * (1.f / (1.f + expf(-v[q])));
      g_h[p][l][m][n+q] = hv;
      if (l == NLY - 1)
        P.out[(size_t)m * 32768 + (size_t)t * 256 + n + q] = hv;
    }
  }
}

// ---------------------------------------------------------------------------
__global__ void seqdec_kernel(Ptrs P) {
  int idx = blockIdx.x * blockDim.x + threadIdx.x;
  int b = idx >> 7, s = idx & 127;
  const float* e = P.out + (size_t)b * 32768 + (size_t)s * 256;
  float a1[8][4], a2[8][4], a3[8][4];
#pragma unroll
  for (int g = 0; g < 8; g++)
#pragma unroll
    for (int o = 0; o < 4; o++) {
      float sum = P.sdb1[o];
#pragma unroll
      for (int m = 0; m < 32; m++) sum += e[g*32+m] * P.sdW1[o*32+m];
      a1[g][o] = sum;
    }
#pragma unroll
  for (int i = 0; i < 8; i++)
#pragma unroll
    for (int o = 0; o < 4; o++) {
      float sum = P.sdb2[o];
#pragma unroll
      for (int j = 0; j < 4; j++) {
        int f = i*4 + j;
        sum += a1[f & 7][f >> 3] * P.sdW2[o*4+j];
      }
      a2[i][o] = sum;
    }
#pragma unroll
  for (int i = 0; i < 8; i++)
#pragma unroll
    for (int o = 0; o < 4; o++) {
      float sum = P.sdb3[o];
#pragma unroll
      for (int j = 0; j < 4; j++) {
        int f = i*4 + j;
        sum += a2[f & 7][f >> 3] * P.sdW3[o*4+j];
      }
      a3[i][o] = sum;
    }
#pragma unroll
  for (int o = 0; o < 4; o++)
#pragma unroll
    for (int wv = 0; wv < 8; wv++) {
      float sum = P.sdb4[wv];
#pragma unroll
      for (int g = 0; g < 8; g++) {
        int f = o*8 + g;
        sum += a3[f >> 2][f & 3] * P.sdW4[wv*8+g];
      }
      P.out[YSEQ_OFF + (size_t)b * 4096 + (size_t)(s*8 + wv) * 4 + o] = sum;
    }
}

// ---------------------------------------------------------------------------
__global__ void onedec_kernel(Ptrs P) {
  int b = blockIdx.x;
  __shared__ float acc[10][4];
  int tid = threadIdx.x;
  if (tid < 10) {
    int s = 118 + tid;
    const float* e = P.out + (size_t)b * 32768 + (size_t)s * 256;
    float o1[8][4], o2[8][4], o3[8][4];
#pragma unroll
    for (int g = 0; g < 8; g++)
#pragma unroll
      for (int o = 0; o < 4; o++) {
        float sum = P.odb1[o];
#pragma unroll
        for (int m = 0; m < 32; m++) sum += e[g*32+m] * P.odW1[o*32+m];
        o1[g][o] = sum;
      }
#pragma unroll
    for (int i = 0; i < 8; i++)
#pragma unroll
      for (int o = 0; o < 4; o++) {
        float sum = P.odb2[o];
#pragma unroll
        for (int j = 0; j < 4; j++) {
          int f = i*4 + j;
          sum += o1[f & 7][f >> 3] * P.odW2[o*4+j];
        }
        o2[i][o] = sum;
      }
#pragma unroll
    for (int i = 0; i < 8; i++)
#pragma unroll
      for (int o = 0; o < 4; o++) {
        float sum = P.odb3[o];
#pragma unroll
        for (int j = 0; j < 4; j++) {
          int f = i*4 + j;
          sum += o2[f & 7][f >> 3] * P.odW3[o*4+j];
        }
        o3[i][o] = fmaxf(sum, 0.f);
      }
#pragma unroll
    for (int c = 0; c < 4; c++) {
      float sum = P.odb4[c];
#pragma unroll
      for (int f = 0; f < 32; f++) sum += o3[f >> 2][f & 3] * P.odW4[c*32+f];
      acc[tid][c] = 1.f / (1.f + expf(-sum));
    }
  }
  __syncthreads();
  if (tid < 4) {
    float s = 0.f;
#pragma unroll
    for (int i = 0; i < 10; i++) s += acc[i][tid];
    P.out[YONE_OFF + (size_t)b * 4 + tid] = s * 0.1f;
  }
}

// ---------------------------------------------------------------------------
extern "C" void kernel_launch(void* const* d_in, const int* in_sizes, int n_in,
                              void* d_out, int out_size) {
  (void)in_sizes; (void)n_in; (void)out_size;
  Ptrs P;
  P.x    = (const float*)d_in[0];
  P.Wih0 = (const float*)d_in[1];
  P.Wih  = (const float*)d_in[2];
  P.Whh  = (const float*)d_in[3];
  P.bih  = (const float*)d_in[4];
  P.bhh  = (const float*)d_in[5];
  P.h0   = (const float*)d_in[6];
  P.aW1  = (const float*)d_in[7];
  P.aW2  = (const float*)d_in[8];
  P.aW3  = (const float*)d_in[9];
  P.aW4  = (const float*)d_in[10];
  P.sdW1 = (const float*)d_in[11];
  P.sdb1 = (const float*)d_in[12];
  P.sdW2 = (const float*)d_in[13];
  P.sdb2 = (const float*)d_in[14];
  P.sdW3 = (const float*)d_in[15];
  P.sdb3 = (const float*)d_in[16];
  P.sdW4 = (const float*)d_in[17];
  P.sdb4 = (const float*)d_in[18];
  P.odW1 = (const float*)d_in[19];
  P.odb1 = (const float*)d_in[20];
  P.odW2 = (const float*)d_in[21];
  P.odb2 = (const float*)d_in[22];
  P.odW3 = (const float*)d_in[23];
  P.odb3 = (const float*)d_in[24];
  P.odW4 = (const float*)d_in[25];
  P.odb4 = (const float*)d_in[26];
  P.out  = (float*)d_out;

  // one-time fold of SortAttn (shuffle,W1,W2,W3) into dense P per layer
  prep_zero<<<6144, 256>>>();
  prep_scatter<<<1536, 256>>>(P);
  prep_w1t<<<1536, 256>>>(P);
  prep_md<<<dim3(64, NLY), 256>>>();
  prep_p<<<dim3(64, NLY), 256>>>();

  for (int w = 0; w < SS + NLY - 1; w++) {
    int lmin = w - (SS - 1); if (lmin < 0) lmin = 0;
    int lmax = (w < NLY - 1) ? w : NLY - 1;
    int nA = lmax - lmin + 1;
    int pp = (w + 1) & 1;
    int p  = w & 1;
    stage1_k<<<dim3(96, nA), 256>>>(P, w, lmin, pp);
    gatesort_k<<<dim3(32, nA), 256>>>(P, w, lmin, pp);
    attn_k<<<dim3(64, nA), 256>>>(lmin);
    a4_k<<<dim3(32, nA), 256>>>(P, w, lmin, p);
  }

  seqdec_kernel<<<128, 256>>>(P);
  onedec_kernel<<<256, 32>>>(P);
}

// round 7
// speedup vs baseline: 2.3318x; 1.7830x over previous
#include <cuda_runtime.h>
#include <cuda_bf16.h>
#include <math.h>

#define BB 256
#define HH 256
#define NLY 6
#define SS 128
#define G3 768
#define PITCH 40   // bf16 smem row pitch (conflict-free for ldmatrix)

struct Ptrs {
  const float *x, *Wih0, *Wih, *Whh, *bih, *bhh, *h0;
  const float *aW1, *aW2, *aW3, *aW4;
  const float *sdW1,*sdb1,*sdW2,*sdb2,*sdW3,*sdb3,*sdW4,*sdb4;
  const float *odW1,*odb1,*odW2,*odb2,*odW3,*odb3,*odW4,*odb4;
  float* out;
};

// scratch (device globals -- no allocation allowed)
__device__ __align__(16) float g_h[2][NLY][BB][HH];
__device__ __align__(16) float g_hpre[NLY][BB][HH];
__device__ __align__(16) float g_sh[NLY][BB][HH];
__device__ __align__(16) float g_Gi[NLY][BB][G3];
__device__ __align__(16) float g_Gh[NLY][BB][G3];
__device__ __align__(16) float g_A3[NLY][BB][512];
// fused-attn precompute
__device__ __align__(16) float g_W2dT[NLY][512][512];
__device__ __align__(16) float g_W3d[NLY][512][512];
__device__ __align__(16) float g_W1T[NLY][256][256];
__device__ __align__(16) float g_Md[NLY][512][512];
__device__ __align__(16) float g_P[NLY][512][512];

#define YSEQ_OFF 8388608ul
#define YONE_OFF 9437184ul

typedef unsigned long long u64;

// ====================== f32x2 helpers (prep GEMMs only) =====================
__device__ __forceinline__ u64 dup2(float a) {
  u64 d; unsigned ai = __float_as_uint(a);
  asm("mov.b64 %0, {%1, %1};" : "=l"(d) : "r"(ai));
  return d;
}
__device__ __forceinline__ void fma2(u64& acc, u64 a, u64 b) {
  asm("fma.rn.f32x2 %0, %1, %2, %0;" : "+l"(acc) : "l"(a), "l"(b));
}
__device__ __forceinline__ void unpack2(u64 v, float& lo, float& hi) {
  unsigned l_, h_;
  asm("mov.b64 {%0, %1}, %2;" : "=r"(l_), "=r"(h_) : "l"(v));
  lo = __uint_as_float(l_); hi = __uint_as_float(h_);
}

__device__ __forceinline__ void gemm64(
    const float* __restrict__ A0, const float* __restrict__ A1, int lda,
    const float* __restrict__ W, int ldb, int K,
    u64 acc[4][2], float* As, float* Bs)
{
  const int t = threadIdx.x;
  const int ar = t >> 2, ak = (t & 3) << 1;
  const int tx = t & 15, ty = t >> 4;
  float2 ra, rb;
  auto loadT = [&](int k0) {
    int c = k0 + ak;
    const float* base = (c < 256) ? (A0 + c) : (A1 + (c - 256));
    ra = *(const float2*)(base + (size_t)ar * lda);
    rb = *(const float2*)(W + (size_t)ar * ldb + k0 + ak);
  };
  auto storeT = [&](int buf) {
    float* as = As + buf * 512;
    float* bs = Bs + buf * 512;
    as[ak*64 + ar] = ra.x; as[(ak+1)*64 + ar] = ra.y;
    bs[ak*64 + ar] = rb.x; bs[(ak+1)*64 + ar] = rb.y;
  };
  auto compute = [&](int buf) {
    const float* as = As + buf * 512 + ty * 4;
    const float* bs = Bs + buf * 512 + tx * 4;
#pragma unroll
    for (int kk = 0; kk < 8; kk++) {
      float4 a4v = *(const float4*)(as + kk * 64);
      ulonglong2 b2 = *(const ulonglong2*)(bs + kk * 64);
      u64 ad;
      ad = dup2(a4v.x); fma2(acc[0][0], ad, b2.x); fma2(acc[0][1], ad, b2.y);
      ad = dup2(a4v.y); fma2(acc[1][0], ad, b2.x); fma2(acc[1][1], ad, b2.y);
      ad = dup2(a4v.z); fma2(acc[2][0], ad, b2.x); fma2(acc[2][1], ad, b2.y);
      ad = dup2(a4v.w); fma2(acc[3][0], ad, b2.x); fma2(acc[3][1], ad, b2.y);
    }
  };
  const int nb = K >> 3;
  loadT(0); storeT(0); __syncthreads();
  for (int kb = 1; kb < nb; kb++) {
    loadT(kb << 3);
    compute((kb - 1) & 1);
    storeT(kb & 1);
    __syncthreads();
  }
  compute((nb - 1) & 1);
}

// ====================== bf16x3 tensor-core GEMM core ========================
__device__ __forceinline__ unsigned s2u(const void* p) {
  return (unsigned)__cvta_generic_to_shared(p);
}
__device__ __forceinline__ void ldmx4(unsigned* r, unsigned a) {
  asm volatile("ldmatrix.sync.aligned.m8n8.x4.shared.b16 {%0,%1,%2,%3}, [%4];"
               : "=r"(r[0]), "=r"(r[1]), "=r"(r[2]), "=r"(r[3]) : "r"(a));
}
__device__ __forceinline__ void mma_bf16(float* c, const unsigned* a, const unsigned* b) {
  asm volatile("mma.sync.aligned.m16n8k16.row.col.f32.bf16.bf16.f32 "
               "{%0,%1,%2,%3}, {%4,%5,%6,%7}, {%8,%9}, {%0,%1,%2,%3};"
               : "+f"(c[0]), "+f"(c[1]), "+f"(c[2]), "+f"(c[3])
               : "r"(a[0]), "r"(a[1]), "r"(a[2]), "r"(a[3]), "r"(b[0]), "r"(b[1]));
}
__device__ __forceinline__ void split8(float4 u, float4 v, uint4& hi4, uint4& lo4) {
  float f[8] = {u.x,u.y,u.z,u.w,v.x,v.y,v.z,v.w};
  unsigned hs[8], ls[8];
#pragma unroll
  for (int i = 0; i < 8; i++) {
    __nv_bfloat16 h = __float2bfloat16_rn(f[i]);
    float r = f[i] - __bfloat162float(h);
    __nv_bfloat16 l = __float2bfloat16_rn(r);
    hs[i] = *(unsigned short*)&h; ls[i] = *(unsigned short*)&l;
  }
  hi4 = make_uint4(hs[0]|(hs[1]<<16), hs[2]|(hs[3]<<16), hs[4]|(hs[5]<<16), hs[6]|(hs[7]<<16));
  lo4 = make_uint4(ls[0]|(ls[1]<<16), ls[2]|(ls[3]<<16), ls[4]|(ls[5]<<16), ls[6]|(ls[7]<<16));
}

// 64x64 output tile, 256 threads (8 warps as 2m x 4n, each warp 32x16).
// C = A @ W^T, fp32 in/out, bf16x3 internally (hi*hi + hi*lo + lo*hi).
// A concat: col c<256 from A0 else A1+(c-256); row stride lda (0 = broadcast).
// W row-major [64 rows pre-offset to n0][K], stride ldw.
__device__ __forceinline__ void mma_tile(
    const float* __restrict__ A0, const float* __restrict__ A1, int lda,
    const float* __restrict__ W, int ldw, int K,
    float c[2][2][4], __nv_bfloat16* sm)
{
  __nv_bfloat16* sAh = sm;
  __nv_bfloat16* sAl = sm + 64*PITCH;
  __nv_bfloat16* sWh = sm + 2*64*PITCH;
  __nv_bfloat16* sWl = sm + 3*64*PITCH;
  const int t = threadIdx.x;
  const int lrow = t >> 2, lcol = (t & 3) << 3;
  const int lane = t & 31, wid = t >> 5;
  const int wm = wid >> 2, wn = wid & 3;
  const unsigned uAh = s2u(sAh), uAl = s2u(sAl), uWh = s2u(sWh), uWl = s2u(sWl);
  // ldmatrix lane addressing
  const int arow = lane & 15, acg = (lane >> 4) << 3;
  const int bq = lane >> 3, brr = lane & 7;
  const int bnrow = wn*16 + ((bq >> 1) << 3) + brr;
  const int bkoff = (bq & 1) << 3;
  const unsigned aoff0 = (unsigned)((wm*32 + arow) * PITCH + acg) * 2;
  const unsigned boff0 = (unsigned)(bnrow * PITCH + bkoff) * 2;

  for (int kb = 0; kb < K; kb += 32) {
    __syncthreads();
    {
      int cidx = kb + lcol;
      const float* base = (cidx < 256) ? (A0 + cidx) : (A1 + (cidx - 256));
      const float* src = base + (size_t)lrow * lda;
      float4 u = *(const float4*)src;
      float4 v = *(const float4*)(src + 4);
      uint4 hi4, lo4; split8(u, v, hi4, lo4);
      *(uint4*)(sAh + lrow*PITCH + lcol) = hi4;
      *(uint4*)(sAl + lrow*PITCH + lcol) = lo4;
      const float* wsrc = W + (size_t)lrow * ldw + kb + lcol;
      u = *(const float4*)wsrc; v = *(const float4*)(wsrc + 4);
      split8(u, v, hi4, lo4);
      *(uint4*)(sWh + lrow*PITCH + lcol) = hi4;
      *(uint4*)(sWl + lrow*PITCH + lcol) = lo4;
    }
    __syncthreads();
#pragma unroll
    for (int kk = 0; kk < 32; kk += 16) {
      unsigned ah[2][4], al[2][4], bh[4], bl[4];
#pragma unroll
      for (int mi = 0; mi < 2; mi++) {
        unsigned off = aoff0 + (unsigned)(mi*16*PITCH + kk) * 2;
        ldmx4(ah[mi], uAh + off);
        ldmx4(al[mi], uAl + off);
      }
      {
        unsigned off = boff0 + (unsigned)kk * 2;
        ldmx4(bh, uWh + off);
        ldmx4(bl, uWl + off);
      }
#pragma unroll
      for (int mi = 0; mi < 2; mi++)
#pragma unroll
        for (int ni = 0; ni < 2; ni++) {
          mma_bf16(c[mi][ni], ah[mi], bh + ni*2);
          mma_bf16(c[mi][ni], ah[mi], bl + ni*2);
          mma_bf16(c[mi][ni], al[mi], bh + ni*2);
        }
    }
  }
}

// ---------------------------------------------------------------------------
// Prep: fold SortAttn shuffles + W1/W2/W3 into dense P (one-time per launch).
// ---------------------------------------------------------------------------
__global__ void prep_zero() {
  int i = blockIdx.x * 256 + threadIdx.x;
  if (i < NLY * 512 * 512) {
    ((float*)g_W2dT)[i] = 0.f;
    ((float*)g_W3d)[i] = 0.f;
  }
}

__global__ void prep_scatter(Ptrs P) {
  int i = blockIdx.x * 256 + threadIdx.x;
  if (i >= NLY * 4 * 128 * 128) return;
  int l = i >> 16; int r = i & 65535;
  int g = r >> 14; int j = (r >> 7) & 127; int m = r & 127;
  int v = g * 128 + m;
  int c = ((v & 3) << 7) + (v >> 2);
  g_W2dT[l][c][g*128 + j] = P.aW2[((size_t)l*128 + j)*128 + m];
  g_W3d[l][g*128 + j][c]  = P.aW3[((size_t)l*128 + j)*128 + m];
}

__global__ void prep_w1t(Ptrs P) {
  int i = blockIdx.x * 256 + threadIdx.x;
  if (i >= NLY * 256 * 256) return;
  int l = i >> 16; int r = i & 65535; int c1 = r >> 8; int k = r & 255;
  g_W1T[l][k][c1] = P.aW1[(size_t)l*65536 + (size_t)c1*256 + k];
}

__global__ void __launch_bounds__(256, 4) prep_md() {
  __shared__ __align__(16) float As[1024], Bs[1024];
  int l = blockIdx.y;
  int i = blockIdx.x;
  int m0 = (i & 7) << 6, n0 = (i >> 3) << 6;
  const float* A0 = &g_W3d[l][m0][0];
  const float* W  = &g_W2dT[l][n0][0];
  u64 acc[4][2] = {};
  gemm64(A0, A0 + 256, 512, W, 512, 512, acc, As, Bs);
  int tx = threadIdx.x & 15, ty = threadIdx.x >> 4;
#pragma unroll
  for (int r = 0; r < 4; r++) {
    float v0,v1,v2,v3;
    unpack2(acc[r][0], v0, v1); unpack2(acc[r][1], v2, v3);
    *(float4*)(&g_Md[l][m0 + ty*4 + r][n0 + tx*4]) = make_float4(v0,v1,v2,v3);
  }
}

__global__ void __launch_bounds__(256, 4) prep_p() {
  __shared__ __align__(16) float As[1024], Bs[1024];
  int l = blockIdx.y;
  int i = blockIdx.x;
  int m0 = (i & 7) << 6;
  int nt = i >> 3;
  int half = nt >> 2;
  const float* A0 = &g_Md[l][m0][half * 256];
  const float* W  = &g_W1T[l][(nt & 3) * 64][0];
  u64 acc[4][2] = {};
  gemm64(A0, A0, 512, W, 256, 256, acc, As, Bs);
  int tx = threadIdx.x & 15, ty = threadIdx.x >> 4;
#pragma unroll
  for (int r = 0; r < 4; r++) {
    float v0,v1,v2,v3;
    unpack2(acc[r][0], v0, v1); unpack2(acc[r][1], v2, v3);
    *(float4*)(&g_P[l][m0 + ty*4 + r][nt*64 + tx*4]) = make_float4(v0,v1,v2,v3);
  }
}

// ---------------------------------------------------------------------------
// Stage 1 (tensor): Gi = inp @ Wih^T ; Gh = h_prev @ Whh^T. grid(96, nA)
// ---------------------------------------------------------------------------
__global__ void __launch_bounds__(256) stage1_k(Ptrs P, int w, int lmin, int pp) {
  __shared__ __align__(16) __nv_bfloat16 sm[4*64*PITCH];
  int l = lmin + blockIdx.y, t = w - l;
  int i = blockIdx.x;
  int which = (i >= 48); i -= which * 48;
  int m0 = (i & 3) << 6, n0 = (i >> 2) << 6;    // n0: 0..704
  const float *A0, *W; int lda, K, ldw; float* out;
  if (!which) {
    if (l == 0) { A0 = P.x + (size_t)t*128 + (size_t)m0*16384; lda = 16384; K = 128;
                  W = P.Wih0 + (size_t)n0 * 128; ldw = 128; }
    else        { A0 = &g_h[pp][l-1][m0][0]; lda = HH; K = HH;
                  W = P.Wih + ((size_t)(l-1)*G3 + n0) * HH; ldw = HH; }
    out = &g_Gi[l][0][0];
  } else {
    if (t == 0) { A0 = P.h0 + l*HH; lda = 0; }
    else        { A0 = &g_h[pp][l][m0][0]; lda = HH; }
    K = HH; W = P.Whh + ((size_t)l*G3 + n0) * HH; ldw = HH;
    out = &g_Gh[l][0][0];
  }
  float c[2][2][4] = {};
  mma_tile(A0, A0, lda, W, ldw, K, c, sm);
  int lane = threadIdx.x & 31, wid = threadIdx.x >> 5;
  int wm = wid >> 2, wn = wid & 3;
  int r0 = m0 + wm*32 + (lane >> 2);
  int c0 = n0 + wn*16 + 2*(lane & 3);
#pragma unroll
  for (int mi = 0; mi < 2; mi++)
#pragma unroll
    for (int ni = 0; ni < 2; ni++) {
      int col = c0 + ni*8;
      *(float2*)(out + (size_t)(r0 + mi*16) * G3 + col)     = make_float2(c[mi][ni][0], c[mi][ni][1]);
      *(float2*)(out + (size_t)(r0 + mi*16 + 8) * G3 + col) = make_float2(c[mi][ni][2], c[mi][ni][3]);
    }
}

// ---------------------------------------------------------------------------
// Stage 2: gates -> hpre, warp-synchronous bitonic sort -> sh. grid(32, nA)
// ---------------------------------------------------------------------------
__global__ void __launch_bounds__(256) gatesort_k(Ptrs P, int w, int lmin, int pp) {
  int l = lmin + blockIdx.y, t = w - l;
  int warp = threadIdx.x >> 5, lane = threadIdx.x & 31;
  int b = blockIdx.x * 8 + warp;
  __shared__ float vbuf[8][256];
  float* v = vbuf[warp];
  const float* bi = P.bih + l * G3;
  const float* bh = P.bhh + l * G3;
#pragma unroll
  for (int q = 0; q < 8; q++) {
    int j = lane + (q << 5);
    float gi0 = g_Gi[l][b][j]      + bi[j];
    float gi1 = g_Gi[l][b][j+256]  + bi[j+256];
    float gi2 = g_Gi[l][b][j+512]  + bi[j+512];
    float gh0 = g_Gh[l][b][j]      + bh[j];
    float gh1 = g_Gh[l][b][j+256]  + bh[j+256];
    float gh2 = g_Gh[l][b][j+512]  + bh[j+512];
    float r = 1.f / (1.f + expf(-(gi0 + gh0)));
    float z = 1.f / (1.f + expf(-(gi1 + gh1)));
    float n = tanhf(gi2 + r * gh2);
    float hp = (t == 0) ? P.h0[l * HH + j] : g_h[pp][l][b][j];
    float hv = (1.f - z) * n + z * hp;
    g_hpre[l][b][j] = hv;
    v[j] = hv;
  }
  __syncwarp();
  for (int k = 2; k <= 256; k <<= 1) {
    for (int jj = k >> 1; jj > 0; jj >>= 1) {
#pragma unroll
      for (int q = 0; q < 8; q++) {
        int idx = lane + (q << 5);
        int ixj = idx ^ jj;
        if (ixj > idx) {
          float a = v[idx], cc = v[ixj];
          bool up = ((idx & k) == 0);
          if ((a > cc) == up) { v[idx] = cc; v[ixj] = a; }
        }
      }
      __syncwarp();
    }
  }
#pragma unroll
  for (int q = 0; q < 8; q++) {
    int j = lane + (q << 5);
    g_sh[l][b][j] = v[j];
  }
}

// ---------------------------------------------------------------------------
// Stage 3 (tensor, fused a1+a2+a3): A3 = relu([hpre|sh] @ P^T). grid(32, nA)
// ---------------------------------------------------------------------------
__global__ void __launch_bounds__(256) attn_k(int lmin) {
  __shared__ __align__(16) __nv_bfloat16 sm[4*64*PITCH];
  int l = lmin + blockIdx.y;
  int i = blockIdx.x;                    // 0..31
  int m0 = (i & 3) << 6, n0 = (i >> 2) << 6;   // n0: 0..448
  const float* A0 = &g_hpre[l][m0][0];
  const float* A1 = &g_sh[l][m0][0];
  const float* W  = &g_P[l][n0][0];
  float c[2][2][4] = {};
  mma_tile(A0, A1, 256, W, 512, 512, c, sm);
  int lane = threadIdx.x & 31, wid = threadIdx.x >> 5;
  int wm = wid >> 2, wn = wid & 3;
  int r0 = m0 + wm*32 + (lane >> 2);
  int c0 = n0 + wn*16 + 2*(lane & 3);
#pragma unroll
  for (int mi = 0; mi < 2; mi++)
#pragma unroll
    for (int ni = 0; ni < 2; ni++) {
      int col = c0 + ni*8;
      float v0 = fmaxf(c[mi][ni][0], 0.f), v1 = fmaxf(c[mi][ni][1], 0.f);
      float v2 = fmaxf(c[mi][ni][2], 0.f), v3 = fmaxf(c[mi][ni][3], 0.f);
      *(float2*)(&g_A3[l][r0 + mi*16][col])     = make_float2(v0, v1);
      *(float2*)(&g_A3[l][r0 + mi*16 + 8][col]) = make_float2(v2, v3);
    }
}

// ---------------------------------------------------------------------------
// Stage 4 (tensor): a4 = A3 @ W4^T ; h = hpre * sigmoid(a4). grid(16, nA)
// ---------------------------------------------------------------------------
__global__ void __launch_bounds__(256) a4_k(Ptrs P, int w, int lmin, int p) {
  __shared__ __align__(16) __nv_bfloat16 sm[4*64*PITCH];
  int l = lmin + blockIdx.y, t = w - l;
  int i = blockIdx.x;                    // 0..15
  int m0 = (i & 3) << 6, n0 = (i >> 2) << 6;   // n0: 0..192
  const float* A0 = &g_A3[l][m0][0];
  const float* W  = P.aW4 + ((size_t)l*256 + n0) * 512;
  float c[2][2][4] = {};
  mma_tile(A0, A0 + 256, 512, W, 512, 512, c, sm);
  int lane = threadIdx.x & 31, wid = threadIdx.x >> 5;
  int wm = wid >> 2, wn = wid & 3;
  int r0 = m0 + wm*32 + (lane >> 2);
  int c0 = n0 + wn*16 + 2*(lane & 3);
#pragma unroll
  for (int mi = 0; mi < 2; mi++)
#pragma unroll
    for (int ni = 0; ni < 2; ni++) {
      int col = c0 + ni*8;
#pragma unroll
      for (int half = 0; half < 2; half++) {
        int row = r0 + mi*16 + half*8;
        float va = c[mi][ni][half*2], vb = c[mi][ni][half*2+1];
        float2 hp = *(float2*)(&g_hpre[l][row][col]);
        float h0v = hp.x * (1.f / (1.f + expf(-va)));
        float h1v = hp.y * (1.f / (1.f + expf(-vb)));
        *(float2*)(&g_h[p][l][row][col]) = make_float2(h0v, h1v);
        if (l == NLY - 1)
          *(float2*)(P.out + (size_t)row * 32768 + (size_t)t * 256 + col) = make_float2(h0v, h1v);
      }
    }
}

// ---------------------------------------------------------------------------
__global__ void seqdec_kernel(Ptrs P) {
  int idx = blockIdx.x * blockDim.x + threadIdx.x;
  int b = idx >> 7, s = idx & 127;
  const float* e = P.out + (size_t)b * 32768 + (size_t)s * 256;
  float a1[8][4], a2[8][4], a3[8][4];
#pragma unroll
  for (int g = 0; g < 8; g++)
#pragma unroll
    for (int o = 0; o < 4; o++) {
      float sum = P.sdb1[o];
#pragma unroll
      for (int m = 0; m < 32; m++) sum += e[g*32+m] * P.sdW1[o*32+m];
      a1[g][o] = sum;
    }
#pragma unroll
  for (int i = 0; i < 8; i++)
#pragma unroll
    for (int o = 0; o < 4; o++) {
      float sum = P.sdb2[o];
#pragma unroll
      for (int j = 0; j < 4; j++) {
        int f = i*4 + j;
        sum += a1[f & 7][f >> 3] * P.sdW2[o*4+j];
      }
      a2[i][o] = sum;
    }
#pragma unroll
  for (int i = 0; i < 8; i++)
#pragma unroll
    for (int o = 0; o < 4; o++) {
      float sum = P.sdb3[o];
#pragma unroll
      for (int j = 0; j < 4; j++) {
        int f = i*4 + j;
        sum += a2[f & 7][f >> 3] * P.sdW3[o*4+j];
      }
      a3[i][o] = sum;
    }
#pragma unroll
  for (int o = 0; o < 4; o++)
#pragma unroll
    for (int wv = 0; wv < 8; wv++) {
      float sum = P.sdb4[wv];
#pragma unroll
      for (int g = 0; g < 8; g++) {
        int f = o*8 + g;
        sum += a3[f >> 2][f & 3] * P.sdW4[wv*8+g];
      }
      P.out[YSEQ_OFF + (size_t)b * 4096 + (size_t)(s*8 + wv) * 4 + o] = sum;
    }
}

// ---------------------------------------------------------------------------
__global__ void onedec_kernel(Ptrs P) {
  int b = blockIdx.x;
  __shared__ float acc[10][4];
  int tid = threadIdx.x;
  if (tid < 10) {
    int s = 118 + tid;
    const float* e = P.out + (size_t)b * 32768 + (size_t)s * 256;
    float o1[8][4], o2[8][4], o3[8][4];
#pragma unroll
    for (int g = 0; g < 8; g++)
#pragma unroll
      for (int o = 0; o < 4; o++) {
        float sum = P.odb1[o];
#pragma unroll
        for (int m = 0; m < 32; m++) sum += e[g*32+m] * P.odW1[o*32+m];
        o1[g][o] = sum;
      }
#pragma unroll
    for (int i = 0; i < 8; i++)
#pragma unroll
      for (int o = 0; o < 4; o++) {
        float sum = P.odb2[o];
#pragma unroll
        for (int j = 0; j < 4; j++) {
          int f = i*4 + j;
          sum += o1[f & 7][f >> 3] * P.odW2[o*4+j];
        }
        o2[i][o] = sum;
      }
#pragma unroll
    for (int i = 0; i < 8; i++)
#pragma unroll
      for (int o = 0; o < 4; o++) {
        float sum = P.odb3[o];
#pragma unroll
        for (int j = 0; j < 4; j++) {
          int f = i*4 + j;
          sum += o2[f & 7][f >> 3] * P.odW3[o*4+j];
        }
        o3[i][o] = fmaxf(sum, 0.f);
      }
#pragma unroll
    for (int c = 0; c < 4; c++) {
      float sum = P.odb4[c];
#pragma unroll
      for (int f = 0; f < 32; f++) sum += o3[f >> 2][f & 3] * P.odW4[c*32+f];
      acc[tid][c] = 1.f / (1.f + expf(-sum));
    }
  }
  __syncthreads();
  if (tid < 4) {
    float s = 0.f;
#pragma unroll
    for (int i = 0; i < 10; i++) s += acc[i][tid];
    P.out[YONE_OFF + (size_t)b * 4 + tid] = s * 0.1f;
  }
}

// ---------------------------------------------------------------------------
extern "C" void kernel_launch(void* const* d_in, const int* in_sizes, int n_in,
                              void* d_out, int out_size) {
  (void)in_sizes; (void)n_in; (void)out_size;
  Ptrs P;
  P.x    = (const float*)d_in[0];
  P.Wih0 = (const float*)d_in[1];
  P.Wih  = (const float*)d_in[2];
  P.Whh  = (const float*)d_in[3];
  P.bih  = (const float*)d_in[4];
  P.bhh  = (const float*)d_in[5];
  P.h0   = (const float*)d_in[6];
  P.aW1  = (const float*)d_in[7];
  P.aW2  = (const float*)d_in[8];
  P.aW3  = (const float*)d_in[9];
  P.aW4  = (const float*)d_in[10];
  P.sdW1 = (const float*)d_in[11];
  P.sdb1 = (const float*)d_in[12];
  P.sdW2 = (const float*)d_in[13];
  P.sdb2 = (const float*)d_in[14];
  P.sdW3 = (const float*)d_in[15];
  P.sdb3 = (const float*)d_in[16];
  P.sdW4 = (const float*)d_in[17];
  P.sdb4 = (const float*)d_in[18];
  P.odW1 = (const float*)d_in[19];
  P.odb1 = (const float*)d_in[20];
  P.odW2 = (const float*)d_in[21];
  P.odb2 = (const float*)d_in[22];
  P.odW3 = (const float*)d_in[23];
  P.odb3 = (const float*)d_in[24];
  P.odW4 = (const float*)d_in[25];
  P.odb4 = (const float*)d_in[26];
  P.out  = (float*)d_out;

  // one-time fold of SortAttn (shuffle,W1,W2,W3) into dense P per layer
  prep_zero<<<6144, 256>>>();
  prep_scatter<<<1536, 256>>>(P);
  prep_w1t<<<1536, 256>>>(P);
  prep_md<<<dim3(64, NLY), 256>>>();
  prep_p<<<dim3(64, NLY), 256>>>();

  for (int w = 0; w < SS + NLY - 1; w++) {
    int lmin = w - (SS - 1); if (lmin < 0) lmin = 0;
    int lmax = (w < NLY - 1) ? w : NLY - 1;
    int nA = lmax - lmin + 1;
    int pp = (w + 1) & 1;
    int p  = w & 1;
    stage1_k<<<dim3(96, nA), 256>>>(P, w, lmin, pp);
    gatesort_k<<<dim3(32, nA), 256>>>(P, w, lmin, pp);
    attn_k<<<dim3(32, nA), 256>>>(lmin);
    a4_k<<<dim3(16, nA), 256>>>(P, w, lmin, p);
  }

  seqdec_kernel<<<128, 256>>>(P);
  onedec_kernel<<<256, 32>>>(P);
}

// round 8
// speedup vs baseline: 2.5695x; 1.1020x over previous
#include <cuda_runtime.h>
#include <cuda_bf16.h>
#include <math.h>

#define BB 256
#define HH 256
#define NLY 6
#define SS 128
#define G3 768
#define PITCH 40   // bf16 smem row pitch (conflict-free for ldmatrix)

struct Ptrs {
  const float *x, *Wih0, *Wih, *Whh, *bih, *bhh, *h0;
  const float *aW1, *aW2, *aW3, *aW4;
  const float *sdW1,*sdb1,*sdW2,*sdb2,*sdW3,*sdb3,*sdW4,*sdb4;
  const float *odW1,*odb1,*odW2,*odb2,*odW3,*odb3,*odW4,*odb4;
  float* out;
};

typedef unsigned long long u64;
typedef __nv_bfloat16 bf16;

// ---------------- fp32 scratch ----------------
__device__ __align__(16) float g_h[2][NLY][BB][HH];
__device__ __align__(16) float g_hpre[NLY][BB][HH];
__device__ __align__(16) float g_Gi[NLY][BB][G3];
__device__ __align__(16) float g_Gh[NLY][BB][G3];
// fused-attn fp32 precompute
__device__ __align__(16) float g_W2dT[NLY][512][512];
__device__ __align__(16) float g_W3d[NLY][512][512];
__device__ __align__(16) float g_W1T[NLY][256][256];
__device__ __align__(16) float g_Md[NLY][512][512];
__device__ __align__(16) float g_P[NLY][512][512];

// ---------------- bf16 hi/lo planes ----------------
__device__ __align__(16) bf16 g_xh[BB][16384],        g_xl[BB][16384];
__device__ __align__(16) bf16 g_W0h[G3][128],         g_W0l[G3][128];
__device__ __align__(16) bf16 g_WihH[NLY-1][G3][HH],  g_WihL[NLY-1][G3][HH];
__device__ __align__(16) bf16 g_WhhH[NLY][G3][HH],    g_WhhL[NLY][G3][HH];
__device__ __align__(16) bf16 g_Ph[NLY][512][512],    g_Pl[NLY][512][512];
__device__ __align__(16) bf16 g_W4h[NLY][256][512],   g_W4l[NLY][256][512];
__device__ __align__(16) bf16 g_h0h[NLY][HH],         g_h0l[NLY][HH];
__device__ __align__(16) bf16 g_hbh[2][NLY][BB][HH],  g_hbl[2][NLY][BB][HH];
__device__ __align__(16) bf16 g_hpreh[NLY][BB][HH],   g_hprel[NLY][BB][HH];
__device__ __align__(16) bf16 g_shh[NLY][BB][HH],     g_shl[NLY][BB][HH];
__device__ __align__(16) bf16 g_A3h[NLY][BB][512],    g_A3l[NLY][BB][512];

#define YSEQ_OFF 8388608ul
#define YONE_OFF 9437184ul

// ====================== f32x2 helpers (prep GEMMs only) =====================
__device__ __forceinline__ u64 dup2(float a) {
  u64 d; unsigned ai = __float_as_uint(a);
  asm("mov.b64 %0, {%1, %1};" : "=l"(d) : "r"(ai));
  return d;
}
__device__ __forceinline__ void fma2(u64& acc, u64 a, u64 b) {
  asm("fma.rn.f32x2 %0, %1, %2, %0;" : "+l"(acc) : "l"(a), "l"(b));
}
__device__ __forceinline__ void unpack2(u64 v, float& lo, float& hi) {
  unsigned l_, h_;
  asm("mov.b64 {%0, %1}, %2;" : "=r"(l_), "=r"(h_) : "l"(v));
  lo = __uint_as_float(l_); hi = __uint_as_float(h_);
}

__device__ __forceinline__ void gemm64(
    const float* __restrict__ A0, const float* __restrict__ A1, int lda,
    const float* __restrict__ W, int ldb, int K,
    u64 acc[4][2], float* As, float* Bs)
{
  const int t = threadIdx.x;
  const int ar = t >> 2, ak = (t & 3) << 1;
  const int tx = t & 15, ty = t >> 4;
  float2 ra, rb;
  auto loadT = [&](int k0) {
    int c = k0 + ak;
    const float* base = (c < 256) ? (A0 + c) : (A1 + (c - 256));
    ra = *(const float2*)(base + (size_t)ar * lda);
    rb = *(const float2*)(W + (size_t)ar * ldb + k0 + ak);
  };
  auto storeT = [&](int buf) {
    float* as = As + buf * 512;
    float* bs = Bs + buf * 512;
    as[ak*64 + ar] = ra.x; as[(ak+1)*64 + ar] = ra.y;
    bs[ak*64 + ar] = rb.x; bs[(ak+1)*64 + ar] = rb.y;
  };
  auto compute = [&](int buf) {
    const float* as = As + buf * 512 + ty * 4;
    const float* bs = Bs + buf * 512 + tx * 4;
#pragma unroll
    for (int kk = 0; kk < 8; kk++) {
      float4 a4v = *(const float4*)(as + kk * 64);
      ulonglong2 b2 = *(const ulonglong2*)(bs + kk * 64);
      u64 ad;
      ad = dup2(a4v.x); fma2(acc[0][0], ad, b2.x); fma2(acc[0][1], ad, b2.y);
      ad = dup2(a4v.y); fma2(acc[1][0], ad, b2.x); fma2(acc[1][1], ad, b2.y);
      ad = dup2(a4v.z); fma2(acc[2][0], ad, b2.x); fma2(acc[2][1], ad, b2.y);
      ad = dup2(a4v.w); fma2(acc[3][0], ad, b2.x); fma2(acc[3][1], ad, b2.y);
    }
  };
  const int nb = K >> 3;
  loadT(0); storeT(0); __syncthreads();
  for (int kb = 1; kb < nb; kb++) {
    loadT(kb << 3);
    compute((kb - 1) & 1);
    storeT(kb & 1);
    __syncthreads();
  }
  compute((nb - 1) & 1);
}

// ====================== bf16 split helpers ==================================
__device__ __forceinline__ void split1(float a, bf16& h, bf16& l) {
  h = __float2bfloat16_rn(a);
  l = __float2bfloat16_rn(a - __bfloat162float(h));
}
__device__ __forceinline__ void split2u(float a, float b, unsigned& hi, unsigned& lo) {
  bf16 ah, al, bh, bl;
  split1(a, ah, al); split1(b, bh, bl);
  hi = (unsigned)*(unsigned short*)&ah | ((unsigned)*(unsigned short*)&bh << 16);
  lo = (unsigned)*(unsigned short*)&al | ((unsigned)*(unsigned short*)&bl << 16);
}

// ====================== bf16x3 tensor-core GEMM core ========================
__device__ __forceinline__ unsigned s2u(const void* p) {
  return (unsigned)__cvta_generic_to_shared(p);
}
__device__ __forceinline__ void ldmx4(unsigned* r, unsigned a) {
  asm volatile("ldmatrix.sync.aligned.m8n8.x4.shared.b16 {%0,%1,%2,%3}, [%4];"
               : "=r"(r[0]), "=r"(r[1]), "=r"(r[2]), "=r"(r[3]) : "r"(a));
}
__device__ __forceinline__ void mma_bf16(float* c, const unsigned* a, const unsigned* b) {
  asm volatile("mma.sync.aligned.m16n8k16.row.col.f32.bf16.bf16.f32 "
               "{%0,%1,%2,%3}, {%4,%5,%6,%7}, {%8,%9}, {%0,%1,%2,%3};"
               : "+f"(c[0]), "+f"(c[1]), "+f"(c[2]), "+f"(c[3])
               : "r"(a[0]), "r"(a[1]), "r"(a[2]), "r"(a[3]), "r"(b[0]), "r"(b[1]));
}

// 64x64 output tile, 256 threads (8 warps: 2m x 4n; warp = 32m x 16n).
// All operands pre-split bf16 hi/lo planes. A concat: col c<256 from (Ah,Al),
// else (A1h,A1l) at c-256. lda in elements (0 = broadcast row). W [n][k] planes.
__device__ __forceinline__ void mma_tileb(
    const bf16* __restrict__ Ah, const bf16* __restrict__ Al,
    const bf16* __restrict__ A1h, const bf16* __restrict__ A1l, int lda,
    const bf16* __restrict__ Wh, const bf16* __restrict__ Wl, int ldw, int K,
    float c[2][2][4], bf16* sm)
{
  bf16* sAh = sm;
  bf16* sAl = sm + 64*PITCH;
  bf16* sWh = sm + 2*64*PITCH;
  bf16* sWl = sm + 3*64*PITCH;
  const int t = threadIdx.x;
  const int lrow = t >> 2, lcol = (t & 3) << 3;      // 64 rows x 32-col chunk, uint4 = 8 bf16
  const int lane = t & 31, wid = t >> 5;
  const int wm = wid >> 2, wn = wid & 3;
  const unsigned uAh = s2u(sAh), uAl = s2u(sAl), uWh = s2u(sWh), uWl = s2u(sWl);
  const int arow = lane & 15, acg = (lane >> 4) << 3;
  const int bq = lane >> 3, brr = lane & 7;
  const int bnrow = wn*16 + ((bq >> 1) << 3) + brr;
  const int bkoff = (bq & 1) << 3;
  const unsigned aoff0 = (unsigned)((wm*32 + arow) * PITCH + acg) * 2;
  const unsigned boff0 = (unsigned)(bnrow * PITCH + bkoff) * 2;

  for (int kb = 0; kb < K; kb += 32) {
    __syncthreads();
    {
      int cidx = kb + lcol;
      const bf16 *bh_, *bl_;
      int cc;
      if (cidx < 256) { bh_ = Ah;  bl_ = Al;  cc = cidx; }
      else            { bh_ = A1h; bl_ = A1l; cc = cidx - 256; }
      size_t ao = (size_t)lrow * lda + cc;
      *(uint4*)(sAh + lrow*PITCH + lcol) = *(const uint4*)(bh_ + ao);
      *(uint4*)(sAl + lrow*PITCH + lcol) = *(const uint4*)(bl_ + ao);
      size_t wo = (size_t)lrow * ldw + kb + lcol;
      *(uint4*)(sWh + lrow*PITCH + lcol) = *(const uint4*)(Wh + wo);
      *(uint4*)(sWl + lrow*PITCH + lcol) = *(const uint4*)(Wl + wo);
    }
    __syncthreads();
#pragma unroll
    for (int kk = 0; kk < 32; kk += 16) {
      unsigned ah[2][4], al[2][4], bh[4], bl[4];
#pragma unroll
      for (int mi = 0; mi < 2; mi++) {
        unsigned off = aoff0 + (unsigned)(mi*16*PITCH + kk) * 2;
        ldmx4(ah[mi], uAh + off);
        ldmx4(al[mi], uAl + off);
      }
      {
        unsigned off = boff0 + (unsigned)kk * 2;
        ldmx4(bh, uWh + off);
        ldmx4(bl, uWl + off);
      }
#pragma unroll
      for (int mi = 0; mi < 2; mi++)
#pragma unroll
        for (int ni = 0; ni < 2; ni++) {
          mma_bf16(c[mi][ni], ah[mi], bh + ni*2);
          mma_bf16(c[mi][ni], ah[mi], bl + ni*2);
          mma_bf16(c[mi][ni], al[mi], bh + ni*2);
        }
    }
  }
}

// ---------------------------------------------------------------------------
// Prep: fold SortAttn shuffles + W1/W2/W3 into dense P (fp32), then split
// all static operands into bf16 hi/lo planes.
// ---------------------------------------------------------------------------
__global__ void prep_zero() {
  int i = blockIdx.x * 256 + threadIdx.x;
  if (i < NLY * 512 * 512) {
    ((float*)g_W2dT)[i] = 0.f;
    ((float*)g_W3d)[i] = 0.f;
  }
}

__global__ void prep_scatter(Ptrs P) {
  int i = blockIdx.x * 256 + threadIdx.x;
  if (i >= NLY * 4 * 128 * 128) return;
  int l = i >> 16; int r = i & 65535;
  int g = r >> 14; int j = (r >> 7) & 127; int m = r & 127;
  int v = g * 128 + m;
  int c = ((v & 3) << 7) + (v >> 2);
  g_W2dT[l][c][g*128 + j] = P.aW2[((size_t)l*128 + j)*128 + m];
  g_W3d[l][g*128 + j][c]  = P.aW3[((size_t)l*128 + j)*128 + m];
}

__global__ void prep_w1t(Ptrs P) {
  int i = blockIdx.x * 256 + threadIdx.x;
  if (i >= NLY * 256 * 256) return;
  int l = i >> 16; int r = i & 65535; int c1 = r >> 8; int k = r & 255;
  g_W1T[l][k][c1] = P.aW1[(size_t)l*65536 + (size_t)c1*256 + k];
}

__global__ void __launch_bounds__(256, 4) prep_md() {
  __shared__ __align__(16) float As[1024], Bs[1024];
  int l = blockIdx.y;
  int i = blockIdx.x;
  int m0 = (i & 7) << 6, n0 = (i >> 3) << 6;
  const float* A0 = &g_W3d[l][m0][0];
  const float* W  = &g_W2dT[l][n0][0];
  u64 acc[4][2] = {};
  gemm64(A0, A0 + 256, 512, W, 512, 512, acc, As, Bs);
  int tx = threadIdx.x & 15, ty = threadIdx.x >> 4;
#pragma unroll
  for (int r = 0; r < 4; r++) {
    float v0,v1,v2,v3;
    unpack2(acc[r][0], v0, v1); unpack2(acc[r][1], v2, v3);
    *(float4*)(&g_Md[l][m0 + ty*4 + r][n0 + tx*4]) = make_float4(v0,v1,v2,v3);
  }
}

__global__ void __launch_bounds__(256, 4) prep_p() {
  __shared__ __align__(16) float As[1024], Bs[1024];
  int l = blockIdx.y;
  int i = blockIdx.x;
  int m0 = (i & 7) << 6;
  int nt = i >> 3;
  int half = nt >> 2;
  const float* A0 = &g_Md[l][m0][half * 256];
  const float* W  = &g_W1T[l][(nt & 3) * 64][0];
  u64 acc[4][2] = {};
  gemm64(A0, A0, 512, W, 256, 256, acc, As, Bs);
  int tx = threadIdx.x & 15, ty = threadIdx.x >> 4;
#pragma unroll
  for (int r = 0; r < 4; r++) {
    float v0,v1,v2,v3;
    unpack2(acc[r][0], v0, v1); unpack2(acc[r][1], v2, v3);
    *(float4*)(&g_P[l][m0 + ty*4 + r][nt*64 + tx*4]) = make_float4(v0,v1,v2,v3);
  }
}

// generic splitter bodies
__global__ void sp_x(Ptrs P) {
  int i = blockIdx.x * 256 + threadIdx.x;
  if (i < BB*16384) split1(P.x[i], ((bf16*)g_xh)[i], ((bf16*)g_xl)[i]);
}
__global__ void sp_w0(Ptrs P) {
  int i = blockIdx.x * 256 + threadIdx.x;
  if (i < G3*128) split1(P.Wih0[i], ((bf16*)g_W0h)[i], ((bf16*)g_W0l)[i]);
}
__global__ void sp_wih(Ptrs P) {
  int i = blockIdx.x * 256 + threadIdx.x;
  if (i < (NLY-1)*G3*HH) split1(P.Wih[i], ((bf16*)g_WihH)[i], ((bf16*)g_WihL)[i]);
}
__global__ void sp_whh(Ptrs P) {
  int i = blockIdx.x * 256 + threadIdx.x;
  if (i < NLY*G3*HH) split1(P.Whh[i], ((bf16*)g_WhhH)[i], ((bf16*)g_WhhL)[i]);
}
__global__ void sp_w4(Ptrs P) {
  int i = blockIdx.x * 256 + threadIdx.x;
  if (i < NLY*256*512) split1(P.aW4[i], ((bf16*)g_W4h)[i], ((bf16*)g_W4l)[i]);
}
__global__ void sp_h0(Ptrs P) {
  int i = blockIdx.x * 256 + threadIdx.x;
  if (i < NLY*HH) split1(P.h0[i], ((bf16*)g_h0h)[i], ((bf16*)g_h0l)[i]);
}
__global__ void sp_P() {
  int i = blockIdx.x * 256 + threadIdx.x;
  if (i < NLY*512*512) split1(((float*)g_P)[i], ((bf16*)g_Ph)[i], ((bf16*)g_Pl)[i]);
}

// ---------------------------------------------------------------------------
// Stage 1 (tensor): Gi = inp @ Wih^T ; Gh = h_prev @ Whh^T. grid(96, nA)
// ---------------------------------------------------------------------------
__global__ void __launch_bounds__(256) stage1_k(Ptrs P, int w, int lmin, int pp) {
  __shared__ __align__(16) bf16 sm[4*64*PITCH];
  int l = lmin + blockIdx.y, t = w - l;
  int i = blockIdx.x;
  int which = (i >= 48); i -= which * 48;
  int m0 = (i & 3) << 6, n0 = (i >> 2) << 6;
  const bf16 *Ah, *Al, *Wh, *Wl; int lda, K, ldw; float* out;
  if (!which) {
    if (l == 0) { Ah = &g_xh[m0][t*128]; Al = &g_xl[m0][t*128]; lda = 16384; K = 128;
                  Wh = &g_W0h[n0][0]; Wl = &g_W0l[n0][0]; ldw = 128; }
    else        { Ah = &g_hbh[pp][l-1][m0][0]; Al = &g_hbl[pp][l-1][m0][0]; lda = HH; K = HH;
                  Wh = &g_WihH[l-1][n0][0]; Wl = &g_WihL[l-1][n0][0]; ldw = HH; }
    out = &g_Gi[l][0][0];
  } else {
    if (t == 0) { Ah = &g_h0h[l][0]; Al = &g_h0l[l][0]; lda = 0; }
    else        { Ah = &g_hbh[pp][l][m0][0]; Al = &g_hbl[pp][l][m0][0]; lda = HH; }
    K = HH; Wh = &g_WhhH[l][n0][0]; Wl = &g_WhhL[l][n0][0]; ldw = HH;
    out = &g_Gh[l][0][0];
  }
  float c[2][2][4] = {};
  mma_tileb(Ah, Al, Ah, Al, lda, Wh, Wl, ldw, K, c, sm);
  int lane = threadIdx.x & 31, wid = threadIdx.x >> 5;
  int wm = wid >> 2, wn = wid & 3;
  int r0 = m0 + wm*32 + (lane >> 2);
  int c0 = n0 + wn*16 + 2*(lane & 3);
#pragma unroll
  for (int mi = 0; mi < 2; mi++)
#pragma unroll
    for (int ni = 0; ni < 2; ni++) {
      int col = c0 + ni*8;
      *(float2*)(out + (size_t)(r0 + mi*16) * G3 + col)     = make_float2(c[mi][ni][0], c[mi][ni][1]);
      *(float2*)(out + (size_t)(r0 + mi*16 + 8) * G3 + col) = make_float2(c[mi][ni][2], c[mi][ni][3]);
    }
}

// ---------------------------------------------------------------------------
// Stage 2: gates -> hpre (fp32 + bf16 planes), bitonic sort -> sh planes.
// ---------------------------------------------------------------------------
__global__ void __launch_bounds__(256) gatesort_k(Ptrs P, int w, int lmin, int pp) {
  int l = lmin + blockIdx.y, t = w - l;
  int warp = threadIdx.x >> 5, lane = threadIdx.x & 31;
  int b = blockIdx.x * 8 + warp;
  __shared__ float vbuf[8][256];
  float* v = vbuf[warp];
  const float* bi = P.bih + l * G3;
  const float* bh = P.bhh + l * G3;
#pragma unroll
  for (int q = 0; q < 8; q++) {
    int j = lane + (q << 5);
    float gi0 = g_Gi[l][b][j]      + bi[j];
    float gi1 = g_Gi[l][b][j+256]  + bi[j+256];
    float gi2 = g_Gi[l][b][j+512]  + bi[j+512];
    float gh0 = g_Gh[l][b][j]      + bh[j];
    float gh1 = g_Gh[l][b][j+256]  + bh[j+256];
    float gh2 = g_Gh[l][b][j+512]  + bh[j+512];
    float r = 1.f / (1.f + expf(-(gi0 + gh0)));
    float z = 1.f / (1.f + expf(-(gi1 + gh1)));
    float n = tanhf(gi2 + r * gh2);
    float hp = (t == 0) ? P.h0[l * HH + j] : g_h[pp][l][b][j];
    float hv = (1.f - z) * n + z * hp;
    g_hpre[l][b][j] = hv;
    split1(hv, g_hpreh[l][b][j], g_hprel[l][b][j]);
    v[j] = hv;
  }
  __syncwarp();
  for (int k = 2; k <= 256; k <<= 1) {
    for (int jj = k >> 1; jj > 0; jj >>= 1) {
#pragma unroll
      for (int q = 0; q < 8; q++) {
        int idx = lane + (q << 5);
        int ixj = idx ^ jj;
        if (ixj > idx) {
          float a = v[idx], cc = v[ixj];
          bool up = ((idx & k) == 0);
          if ((a > cc) == up) { v[idx] = cc; v[ixj] = a; }
        }
      }
      __syncwarp();
    }
  }
#pragma unroll
  for (int q = 0; q < 8; q++) {
    int j = lane + (q << 5);
    split1(v[j], g_shh[l][b][j], g_shl[l][b][j]);
  }
}

// ---------------------------------------------------------------------------
// Stage 3 (tensor, fused a1+a2+a3): A3 = relu([hpre|sh] @ P^T). grid(32, nA)
// ---------------------------------------------------------------------------
__global__ void __launch_bounds__(256) attn_k(int lmin) {
  __shared__ __align__(16) bf16 sm[4*64*PITCH];
  int l = lmin + blockIdx.y;
  int i = blockIdx.x;
  int m0 = (i & 3) << 6, n0 = (i >> 2) << 6;
  float c[2][2][4] = {};
  mma_tileb(&g_hpreh[l][m0][0], &g_hprel[l][m0][0],
            &g_shh[l][m0][0],   &g_shl[l][m0][0], 256,
            &g_Ph[l][n0][0],    &g_Pl[l][n0][0], 512, 512, c, sm);
  int lane = threadIdx.x & 31, wid = threadIdx.x >> 5;
  int wm = wid >> 2, wn = wid & 3;
  int r0 = m0 + wm*32 + (lane >> 2);
  int c0 = n0 + wn*16 + 2*(lane & 3);
#pragma unroll
  for (int mi = 0; mi < 2; mi++)
#pragma unroll
    for (int ni = 0; ni < 2; ni++) {
      int col = c0 + ni*8;
#pragma unroll
      for (int half = 0; half < 2; half++) {
        int row = r0 + mi*16 + half*8;
        float v0 = fmaxf(c[mi][ni][half*2], 0.f);
        float v1 = fmaxf(c[mi][ni][half*2+1], 0.f);
        unsigned hi, lo; split2u(v0, v1, hi, lo);
        *(unsigned*)(&g_A3h[l][row][col]) = hi;
        *(unsigned*)(&g_A3l[l][row][col]) = lo;
      }
    }
}

// ---------------------------------------------------------------------------
// Stage 4 (tensor): a4 = A3 @ W4^T ; h = hpre * sigmoid(a4). grid(16, nA)
// ---------------------------------------------------------------------------
__global__ void __launch_bounds__(256) a4_k(Ptrs P, int w, int lmin, int p) {
  __shared__ __align__(16) bf16 sm[4*64*PITCH];
  int l = lmin + blockIdx.y, t = w - l;
  int i = blockIdx.x;
  int m0 = (i & 3) << 6, n0 = (i >> 2) << 6;
  float c[2][2][4] = {};
  mma_tileb(&g_A3h[l][m0][0], &g_A3l[l][m0][0],
            &g_A3h[l][m0][256], &g_A3l[l][m0][256], 512,
            &g_W4h[l][n0][0], &g_W4l[l][n0][0], 512, 512, c, sm);
  int lane = threadIdx.x & 31, wid = threadIdx.x >> 5;
  int wm = wid >> 2, wn = wid & 3;
  int r0 = m0 + wm*32 + (lane >> 2);
  int c0 = n0 + wn*16 + 2*(lane & 3);
#pragma unroll
  for (int mi = 0; mi < 2; mi++)
#pragma unroll
    for (int ni = 0; ni < 2; ni++) {
      int col = c0 + ni*8;
#pragma unroll
      for (int half = 0; half < 2; half++) {
        int row = r0 + mi*16 + half*8;
        float va = c[mi][ni][half*2], vb = c[mi][ni][half*2+1];
        float2 hp = *(float2*)(&g_hpre[l][row][col]);
        float h0v = hp.x * (1.f / (1.f + expf(-va)));
        float h1v = hp.y * (1.f / (1.f + expf(-vb)));
        *(float2*)(&g_h[p][l][row][col]) = make_float2(h0v, h1v);
        unsigned hi, lo; split2u(h0v, h1v, hi, lo);
        *(unsigned*)(&g_hbh[p][l][row][col]) = hi;
        *(unsigned*)(&g_hbl[p][l][row][col]) = lo;
        if (l == NLY - 1)
          *(float2*)(P.out + (size_t)row * 32768 + (size_t)t * 256 + col) = make_float2(h0v, h1v);
      }
    }
}

// ---------------------------------------------------------------------------
__global__ void seqdec_kernel(Ptrs P) {
  int idx = blockIdx.x * blockDim.x + threadIdx.x;
  int b = idx >> 7, s = idx & 127;
  const float* e = P.out + (size_t)b * 32768 + (size_t)s * 256;
  float a1[8][4], a2[8][4], a3[8][4];
#pragma unroll
  for (int g = 0; g < 8; g++)
#pragma unroll
    for (int o = 0; o < 4; o++) {
      float sum = P.sdb1[o];
#pragma unroll
      for (int m = 0; m < 32; m++) sum += e[g*32+m] * P.sdW1[o*32+m];
      a1[g][o] = sum;
    }
#pragma unroll
  for (int i = 0; i < 8; i++)
#pragma unroll
    for (int o = 0; o < 4; o++) {
      float sum = P.sdb2[o];
#pragma unroll
      for (int j = 0; j < 4; j++) {
        int f = i*4 + j;
        sum += a1[f & 7][f >> 3] * P.sdW2[o*4+j];
      }
      a2[i][o] = sum;
    }
#pragma unroll
  for (int i = 0; i < 8; i++)
#pragma unroll
    for (int o = 0; o < 4; o++) {
      float sum = P.sdb3[o];
#pragma unroll
      for (int j = 0; j < 4; j++) {
        int f = i*4 + j;
        sum += a2[f & 7][f >> 3] * P.sdW3[o*4+j];
      }
      a3[i][o] = sum;
    }
#pragma unroll
  for (int o = 0; o < 4; o++)
#pragma unroll
    for (int wv = 0; wv < 8; wv++) {
      float sum = P.sdb4[wv];
#pragma unroll
      for (int g = 0; g < 8; g++) {
        int f = o*8 + g;
        sum += a3[f >> 2][f & 3] * P.sdW4[wv*8+g];
      }
      P.out[YSEQ_OFF + (size_t)b * 4096 + (size_t)(s*8 + wv) * 4 + o] = sum;
    }
}

// ---------------------------------------------------------------------------
__global__ void onedec_kernel(Ptrs P) {
  int b = blockIdx.x;
  __shared__ float acc[10][4];
  int tid = threadIdx.x;
  if (tid < 10) {
    int s = 118 + tid;
    const float* e = P.out + (size_t)b * 32768 + (size_t)s * 256;
    float o1[8][4], o2[8][4], o3[8][4];
#pragma unroll
    for (int g = 0; g < 8; g++)
#pragma unroll
      for (int o = 0; o < 4; o++) {
        float sum = P.odb1[o];
#pragma unroll
        for (int m = 0; m < 32; m++) sum += e[g*32+m] * P.odW1[o*32+m];
        o1[g][o] = sum;
      }
#pragma unroll
    for (int i = 0; i < 8; i++)
#pragma unroll
      for (int o = 0; o < 4; o++) {
        float sum = P.odb2[o];
#pragma unroll
        for (int j = 0; j < 4; j++) {
          int f = i*4 + j;
          sum += o1[f & 7][f >> 3] * P.odW2[o*4+j];
        }
        o2[i][o] = sum;
      }
#pragma unroll
    for (int i = 0; i < 8; i++)
#pragma unroll
      for (int o = 0; o < 4; o++) {
        float sum = P.odb3[o];
#pragma unroll
        for (int j = 0; j < 4; j++) {
          int f = i*4 + j;
          sum += o2[f & 7][f >> 3] * P.odW3[o*4+j];
        }
        o3[i][o] = fmaxf(sum, 0.f);
      }
#pragma unroll
    for (int c = 0; c < 4; c++) {
      float sum = P.odb4[c];
#pragma unroll
      for (int f = 0; f < 32; f++) sum += o3[f >> 2][f & 3] * P.odW4[c*32+f];
      acc[tid][c] = 1.f / (1.f + expf(-sum));
    }
  }
  __syncthreads();
  if (tid < 4) {
    float s = 0.f;
#pragma unroll
    for (int i = 0; i < 10; i++) s += acc[i][tid];
    P.out[YONE_OFF + (size_t)b * 4 + tid] = s * 0.1f;
  }
}

// ---------------------------------------------------------------------------
extern "C" void kernel_launch(void* const* d_in, const int* in_sizes, int n_in,
                              void* d_out, int out_size) {
  (void)in_sizes; (void)n_in; (void)out_size;
  Ptrs P;
  P.x    = (const float*)d_in[0];
  P.Wih0 = (const float*)d_in[1];
  P.Wih  = (const float*)d_in[2];
  P.Whh  = (const float*)d_in[3];
  P.bih  = (const float*)d_in[4];
  P.bhh  = (const float*)d_in[5];
  P.h0   = (const float*)d_in[6];
  P.aW1  = (const float*)d_in[7];
  P.aW2  = (const float*)d_in[8];
  P.aW3  = (const float*)d_in[9];
  P.aW4  = (const float*)d_in[10];
  P.sdW1 = (const float*)d_in[11];
  P.sdb1 = (const float*)d_in[12];
  P.sdW2 = (const float*)d_in[13];
  P.sdb2 = (const float*)d_in[14];
  P.sdW3 = (const float*)d_in[15];
  P.sdb3 = (const float*)d_in[16];
  P.sdW4 = (const float*)d_in[17];
  P.sdb4 = (const float*)d_in[18];
  P.odW1 = (const float*)d_in[19];
  P.odb1 = (const float*)d_in[20];
  P.odW2 = (const float*)d_in[21];
  P.odb2 = (const float*)d_in[22];
  P.odW3 = (const float*)d_in[23];
  P.odb3 = (const float*)d_in[24];
  P.odW4 = (const float*)d_in[25];
  P.odb4 = (const float*)d_in[26];
  P.out  = (float*)d_out;

  // one-time: fold SortAttn into dense P; split all static operands to bf16 planes
  prep_zero<<<6144, 256>>>();
  prep_scatter<<<1536, 256>>>(P);
  prep_w1t<<<1536, 256>>>(P);
  prep_md<<<dim3(64, NLY), 256>>>();
  prep_p<<<dim3(64, NLY), 256>>>();
  sp_x<<<16384, 256>>>(P);
  sp_w0<<<384, 256>>>(P);
  sp_wih<<<3840, 256>>>(P);
  sp_whh<<<4608, 256>>>(P);
  sp_w4<<<3072, 256>>>(P);
  sp_h0<<<6, 256>>>(P);
  sp_P<<<6144, 256>>>();

  for (int w = 0; w < SS + NLY - 1; w++) {
    int lmin = w - (SS - 1); if (lmin < 0) lmin = 0;
    int lmax = (w < NLY - 1) ? w : NLY - 1;
    int nA = lmax - lmin + 1;
    int pp = (w + 1) & 1;
    int p  = w & 1;
    stage1_k<<<dim3(96, nA), 256>>>(P, w, lmin, pp);
    gatesort_k<<<dim3(32, nA), 256>>>(P, w, lmin, pp);
    attn_k<<<dim3(32, nA), 256>>>(lmin);
    a4_k<<<dim3(16, nA), 256>>>(P, w, lmin, p);
  }

  seqdec_kernel<<<128, 256>>>(P);
  onedec_kernel<<<256, 32>>>(P);
}

// round 9
// speedup vs baseline: 2.7058x; 1.0530x over previous
#include <cuda_runtime.h>
#include <cuda_bf16.h>
#include <math.h>

#define BB 256
#define HH 256
#define NLY 6
#define SS 128
#define G3 768
#define PITCH 40   // bf16 smem row pitch (conflict-free for ldmatrix)

struct Ptrs {
  const float *x, *Wih0, *Wih, *Whh, *bih, *bhh, *h0;
  const float *aW1, *aW2, *aW3, *aW4;
  const float *sdW1,*sdb1,*sdW2,*sdb2,*sdW3,*sdb3,*sdW4,*sdb4;
  const float *odW1,*odb1,*odW2,*odb2,*odW3,*odb3,*odW4,*odb4;
  float* out;
};

typedef unsigned long long u64;
typedef __nv_bfloat16 bf16;

// ---------------- fp32 scratch ----------------
__device__ __align__(16) float g_h[2][NLY][BB][HH];
__device__ __align__(16) float g_hpre[NLY][BB][HH];
__device__ __align__(16) float g_Gi[NLY][BB][G3];
__device__ __align__(16) float g_Gh[NLY][BB][G3];
// fused-attn fp32 precompute
__device__ __align__(16) float g_W2dT[NLY][512][512];
__device__ __align__(16) float g_W3d[NLY][512][512];
__device__ __align__(16) float g_W1T[NLY][256][256];
__device__ __align__(16) float g_Md[NLY][512][512];
__device__ __align__(16) float g_P[NLY][512][512];

// ---------------- bf16 hi/lo planes ----------------
__device__ __align__(16) bf16 g_xh[BB][16384],        g_xl[BB][16384];
__device__ __align__(16) bf16 g_W0h[G3][128],         g_W0l[G3][128];
__device__ __align__(16) bf16 g_WihH[NLY-1][G3][HH],  g_WihL[NLY-1][G3][HH];
__device__ __align__(16) bf16 g_WhhH[NLY][G3][HH],    g_WhhL[NLY][G3][HH];
__device__ __align__(16) bf16 g_Ph[NLY][512][512],    g_Pl[NLY][512][512];
__device__ __align__(16) bf16 g_W4h[NLY][256][512],   g_W4l[NLY][256][512];
__device__ __align__(16) bf16 g_h0h[NLY][HH],         g_h0l[NLY][HH];
__device__ __align__(16) bf16 g_hbh[2][NLY][BB][HH],  g_hbl[2][NLY][BB][HH];
__device__ __align__(16) bf16 g_hpreh[NLY][BB][HH],   g_hprel[NLY][BB][HH];
__device__ __align__(16) bf16 g_shh[NLY][BB][HH],     g_shl[NLY][BB][HH];
__device__ __align__(16) bf16 g_A3h[NLY][BB][512],    g_A3l[NLY][BB][512];

#define YSEQ_OFF 8388608ul
#define YONE_OFF 9437184ul

// ====================== f32x2 helpers (prep GEMMs only) =====================
__device__ __forceinline__ u64 dup2(float a) {
  u64 d; unsigned ai = __float_as_uint(a);
  asm("mov.b64 %0, {%1, %1};" : "=l"(d) : "r"(ai));
  return d;
}
__device__ __forceinline__ void fma2(u64& acc, u64 a, u64 b) {
  asm("fma.rn.f32x2 %0, %1, %2, %0;" : "+l"(acc) : "l"(a), "l"(b));
}
__device__ __forceinline__ void unpack2(u64 v, float& lo, float& hi) {
  unsigned l_, h_;
  asm("mov.b64 {%0, %1}, %2;" : "=r"(l_), "=r"(h_) : "l"(v));
  lo = __uint_as_float(l_); hi = __uint_as_float(h_);
}

__device__ __forceinline__ void gemm64(
    const float* __restrict__ A0, const float* __restrict__ A1, int lda,
    const float* __restrict__ W, int ldb, int K,
    u64 acc[4][2], float* As, float* Bs)
{
  const int t = threadIdx.x;
  const int ar = t >> 2, ak = (t & 3) << 1;
  const int tx = t & 15, ty = t >> 4;
  float2 ra, rb;
  auto loadT = [&](int k0) {
    int c = k0 + ak;
    const float* base = (c < 256) ? (A0 + c) : (A1 + (c - 256));
    ra = *(const float2*)(base + (size_t)ar * lda);
    rb = *(const float2*)(W + (size_t)ar * ldb + k0 + ak);
  };
  auto storeT = [&](int buf) {
    float* as = As + buf * 512;
    float* bs = Bs + buf * 512;
    as[ak*64 + ar] = ra.x; as[(ak+1)*64 + ar] = ra.y;
    bs[ak*64 + ar] = rb.x; bs[(ak+1)*64 + ar] = rb.y;
  };
  auto compute = [&](int buf) {
    const float* as = As + buf * 512 + ty * 4;
    const float* bs = Bs + buf * 512 + tx * 4;
#pragma unroll
    for (int kk = 0; kk < 8; kk++) {
      float4 a4v = *(const float4*)(as + kk * 64);
      ulonglong2 b2 = *(const ulonglong2*)(bs + kk * 64);
      u64 ad;
      ad = dup2(a4v.x); fma2(acc[0][0], ad, b2.x); fma2(acc[0][1], ad, b2.y);
      ad = dup2(a4v.y); fma2(acc[1][0], ad, b2.x); fma2(acc[1][1], ad, b2.y);
      ad = dup2(a4v.z); fma2(acc[2][0], ad, b2.x); fma2(acc[2][1], ad, b2.y);
      ad = dup2(a4v.w); fma2(acc[3][0], ad, b2.x); fma2(acc[3][1], ad, b2.y);
    }
  };
  const int nb = K >> 3;
  loadT(0); storeT(0); __syncthreads();
  for (int kb = 1; kb < nb; kb++) {
    loadT(kb << 3);
    compute((kb - 1) & 1);
    storeT(kb & 1);
    __syncthreads();
  }
  compute((nb - 1) & 1);
}

// ====================== bf16 split helpers ==================================
__device__ __forceinline__ void split1(float a, bf16& h, bf16& l) {
  h = __float2bfloat16_rn(a);
  l = __float2bfloat16_rn(a - __bfloat162float(h));
}
__device__ __forceinline__ void split2u(float a, float b, unsigned& hi, unsigned& lo) {
  bf16 ah, al, bh, bl;
  split1(a, ah, al); split1(b, bh, bl);
  hi = (unsigned)*(unsigned short*)&ah | ((unsigned)*(unsigned short*)&bh << 16);
  lo = (unsigned)*(unsigned short*)&al | ((unsigned)*(unsigned short*)&bl << 16);
}

// ====================== bf16x3 tensor-core GEMM core ========================
__device__ __forceinline__ unsigned s2u(const void* p) {
  return (unsigned)__cvta_generic_to_shared(p);
}
__device__ __forceinline__ void ldmx4(unsigned* r, unsigned a) {
  asm volatile("ldmatrix.sync.aligned.m8n8.x4.shared.b16 {%0,%1,%2,%3}, [%4];"
               : "=r"(r[0]), "=r"(r[1]), "=r"(r[2]), "=r"(r[3]) : "r"(a));
}
__device__ __forceinline__ void mma_bf16(float* c, const unsigned* a, const unsigned* b) {
  asm volatile("mma.sync.aligned.m16n8k16.row.col.f32.bf16.bf16.f32 "
               "{%0,%1,%2,%3}, {%4,%5,%6,%7}, {%8,%9}, {%0,%1,%2,%3};"
               : "+f"(c[0]), "+f"(c[1]), "+f"(c[2]), "+f"(c[3])
               : "r"(a[0]), "r"(a[1]), "r"(a[2]), "r"(a[3]), "r"(b[0]), "r"(b[1]));
}

// 64x64 output tile, 256 threads (8 warps: 2m x 4n; warp = 32m x 16n).
// Pre-split bf16 hi/lo planes, DOUBLE-BUFFERED gmem->reg->smem staging.
// A concat: col c<256 from (Ah,Al), else (A1h,A1l) at c-256. lda in elements
// (0 = broadcast row). W [n][k] planes, stride ldw.
#define SMBUF (4*64*PITCH)
__device__ __forceinline__ void mma_tileb(
    const bf16* __restrict__ Ah, const bf16* __restrict__ Al,
    const bf16* __restrict__ A1h, const bf16* __restrict__ A1l, int lda,
    const bf16* __restrict__ Wh, const bf16* __restrict__ Wl, int ldw, int K,
    float c[2][2][4], bf16* sm)
{
  const int t = threadIdx.x;
  const int lrow = t >> 2, lcol = (t & 3) << 3;   // 64 rows x 32-col chunk, uint4 = 8 bf16
  const int lane = t & 31, wid = t >> 5;
  const int wm = wid >> 2, wn = wid & 3;
  const int arow = lane & 15, acg = (lane >> 4) << 3;
  const int bq = lane >> 3, brr = lane & 7;
  const int bnrow = wn*16 + ((bq >> 1) << 3) + brr;
  const int bkoff = (bq & 1) << 3;
  const unsigned aoff0 = (unsigned)((wm*32 + arow) * PITCH + acg) * 2;
  const unsigned boff0 = (unsigned)(bnrow * PITCH + bkoff) * 2;
  const unsigned base = s2u(sm);

  uint4 rAh, rAl, rWh, rWl;
  auto loadG = [&](int kb) {
    int cidx = kb + lcol;
    const bf16 *bh_, *bl_;
    int cc;
    if (cidx < 256) { bh_ = Ah;  bl_ = Al;  cc = cidx; }
    else            { bh_ = A1h; bl_ = A1l; cc = cidx - 256; }
    size_t ao = (size_t)lrow * lda + cc;
    rAh = *(const uint4*)(bh_ + ao);
    rAl = *(const uint4*)(bl_ + ao);
    size_t wo = (size_t)lrow * ldw + kb + lcol;
    rWh = *(const uint4*)(Wh + wo);
    rWl = *(const uint4*)(Wl + wo);
  };
  auto storeS = [&](int buf) {
    bf16* s = sm + buf * SMBUF;
    int off = lrow*PITCH + lcol;
    *(uint4*)(s + off)             = rAh;
    *(uint4*)(s + 64*PITCH + off)  = rAl;
    *(uint4*)(s + 2*64*PITCH + off) = rWh;
    *(uint4*)(s + 3*64*PITCH + off) = rWl;
  };
  auto compute = [&](int buf) {
    unsigned b0 = base + (unsigned)(buf * SMBUF) * 2;
    unsigned uAh = b0, uAl = b0 + 64*PITCH*2, uWh = b0 + 2*64*PITCH*2, uWl = b0 + 3*64*PITCH*2;
#pragma unroll
    for (int kk = 0; kk < 32; kk += 16) {
      unsigned ah[2][4], al[2][4], bh[4], bl[4];
#pragma unroll
      for (int mi = 0; mi < 2; mi++) {
        unsigned off = aoff0 + (unsigned)(mi*16*PITCH + kk) * 2;
        ldmx4(ah[mi], uAh + off);
        ldmx4(al[mi], uAl + off);
      }
      {
        unsigned off = boff0 + (unsigned)kk * 2;
        ldmx4(bh, uWh + off);
        ldmx4(bl, uWl + off);
      }
#pragma unroll
      for (int mi = 0; mi < 2; mi++)
#pragma unroll
        for (int ni = 0; ni < 2; ni++) {
          mma_bf16(c[mi][ni], ah[mi], bh + ni*2);
          mma_bf16(c[mi][ni], ah[mi], bl + ni*2);
          mma_bf16(c[mi][ni], al[mi], bh + ni*2);
        }
    }
  };

  const int nb = K >> 5;
  loadG(0); storeS(0); __syncthreads();
  for (int kb = 1; kb < nb; kb++) {
    loadG(kb << 5);
    compute((kb - 1) & 1);
    storeS(kb & 1);
    __syncthreads();
  }
  compute((nb - 1) & 1);
}

// ---------------------------------------------------------------------------
// Prep kernels (one-time per launch)
// ---------------------------------------------------------------------------
__global__ void prep_zero() {
  int i = blockIdx.x * 256 + threadIdx.x;
  if (i < NLY * 512 * 512) {
    ((float*)g_W2dT)[i] = 0.f;
    ((float*)g_W3d)[i] = 0.f;
  }
}

__global__ void prep_scatter(Ptrs P) {
  int i = blockIdx.x * 256 + threadIdx.x;
  if (i >= NLY * 4 * 128 * 128) return;
  int l = i >> 16; int r = i & 65535;
  int g = r >> 14; int j = (r >> 7) & 127; int m = r & 127;
  int v = g * 128 + m;
  int c = ((v & 3) << 7) + (v >> 2);
  g_W2dT[l][c][g*128 + j] = P.aW2[((size_t)l*128 + j)*128 + m];
  g_W3d[l][g*128 + j][c]  = P.aW3[((size_t)l*128 + j)*128 + m];
}

__global__ void prep_w1t(Ptrs P) {
  int i = blockIdx.x * 256 + threadIdx.x;
  if (i >= NLY * 256 * 256) return;
  int l = i >> 16; int r = i & 65535; int c1 = r >> 8; int k = r & 255;
  g_W1T[l][k][c1] = P.aW1[(size_t)l*65536 + (size_t)c1*256 + k];
}

__global__ void __launch_bounds__(256, 4) prep_md() {
  __shared__ __align__(16) float As[1024], Bs[1024];
  int l = blockIdx.y;
  int i = blockIdx.x;
  int m0 = (i & 7) << 6, n0 = (i >> 3) << 6;
  const float* A0 = &g_W3d[l][m0][0];
  const float* W  = &g_W2dT[l][n0][0];
  u64 acc[4][2] = {};
  gemm64(A0, A0 + 256, 512, W, 512, 512, acc, As, Bs);
  int tx = threadIdx.x & 15, ty = threadIdx.x >> 4;
#pragma unroll
  for (int r = 0; r < 4; r++) {
    float v0,v1,v2,v3;
    unpack2(acc[r][0], v0, v1); unpack2(acc[r][1], v2, v3);
    *(float4*)(&g_Md[l][m0 + ty*4 + r][n0 + tx*4]) = make_float4(v0,v1,v2,v3);
  }
}

__global__ void __launch_bounds__(256, 4) prep_p() {
  __shared__ __align__(16) float As[1024], Bs[1024];
  int l = blockIdx.y;
  int i = blockIdx.x;
  int m0 = (i & 7) << 6;
  int nt = i >> 3;
  int half = nt >> 2;
  const float* A0 = &g_Md[l][m0][half * 256];
  const float* W  = &g_W1T[l][(nt & 3) * 64][0];
  u64 acc[4][2] = {};
  gemm64(A0, A0, 512, W, 256, 256, acc, As, Bs);
  int tx = threadIdx.x & 15, ty = threadIdx.x >> 4;
#pragma unroll
  for (int r = 0; r < 4; r++) {
    float v0,v1,v2,v3;
    unpack2(acc[r][0], v0, v1); unpack2(acc[r][1], v2, v3);
    *(float4*)(&g_P[l][m0 + ty*4 + r][nt*64 + tx*4]) = make_float4(v0,v1,v2,v3);
  }
}

// splitters
__global__ void sp_x(Ptrs P) {
  int i = blockIdx.x * 256 + threadIdx.x;
  if (i < BB*16384) split1(P.x[i], ((bf16*)g_xh)[i], ((bf16*)g_xl)[i]);
}
__global__ void sp_w0(Ptrs P) {
  int i = blockIdx.x * 256 + threadIdx.x;
  if (i < G3*128) split1(P.Wih0[i], ((bf16*)g_W0h)[i], ((bf16*)g_W0l)[i]);
}
__global__ void sp_wih(Ptrs P) {
  int i = blockIdx.x * 256 + threadIdx.x;
  if (i < (NLY-1)*G3*HH) split1(P.Wih[i], ((bf16*)g_WihH)[i], ((bf16*)g_WihL)[i]);
}
__global__ void sp_whh(Ptrs P) {
  int i = blockIdx.x * 256 + threadIdx.x;
  if (i < NLY*G3*HH) split1(P.Whh[i], ((bf16*)g_WhhH)[i], ((bf16*)g_WhhL)[i]);
}
__global__ void sp_w4(Ptrs P) {
  int i = blockIdx.x * 256 + threadIdx.x;
  if (i < NLY*256*512) split1(P.aW4[i], ((bf16*)g_W4h)[i], ((bf16*)g_W4l)[i]);
}
__global__ void sp_h0(Ptrs P) {
  int i = blockIdx.x * 256 + threadIdx.x;
  if (i < NLY*HH) split1(P.h0[i], ((bf16*)g_h0h)[i], ((bf16*)g_h0l)[i]);
}
__global__ void sp_P() {
  int i = blockIdx.x * 256 + threadIdx.x;
  if (i < NLY*512*512) split1(((float*)g_P)[i], ((bf16*)g_Ph)[i], ((bf16*)g_Pl)[i]);
}

// ---------------------------------------------------------------------------
// Stage 1 (tensor): Gi = inp @ Wih^T ; Gh = h_prev @ Whh^T. grid(96, nA)
// ---------------------------------------------------------------------------
__global__ void __launch_bounds__(256) stage1_k(Ptrs P, int w, int lmin, int pp) {
  __shared__ __align__(16) bf16 sm[2*SMBUF];
  int l = lmin + blockIdx.y, t = w - l;
  int i = blockIdx.x;
  int which = (i >= 48); i -= which * 48;
  int m0 = (i & 3) << 6, n0 = (i >> 2) << 6;
  const bf16 *Ah, *Al, *Wh, *Wl; int lda, K, ldw; float* out;
  if (!which) {
    if (l == 0) { Ah = &g_xh[m0][t*128]; Al = &g_xl[m0][t*128]; lda = 16384; K = 128;
                  Wh = &g_W0h[n0][0]; Wl = &g_W0l[n0][0]; ldw = 128; }
    else        { Ah = &g_hbh[pp][l-1][m0][0]; Al = &g_hbl[pp][l-1][m0][0]; lda = HH; K = HH;
                  Wh = &g_WihH[l-1][n0][0]; Wl = &g_WihL[l-1][n0][0]; ldw = HH; }
    out = &g_Gi[l][0][0];
  } else {
    if (t == 0) { Ah = &g_h0h[l][0]; Al = &g_h0l[l][0]; lda = 0; }
    else        { Ah = &g_hbh[pp][l][m0][0]; Al = &g_hbl[pp][l][m0][0]; lda = HH; }
    K = HH; Wh = &g_WhhH[l][n0][0]; Wl = &g_WhhL[l][n0][0]; ldw = HH;
    out = &g_Gh[l][0][0];
  }
  float c[2][2][4] = {};
  mma_tileb(Ah, Al, Ah, Al, lda, Wh, Wl, ldw, K, c, sm);
  int lane = threadIdx.x & 31, wid = threadIdx.x >> 5;
  int wm = wid >> 2, wn = wid & 3;
  int r0 = m0 + wm*32 + (lane >> 2);
  int c0 = n0 + wn*16 + 2*(lane & 3);
#pragma unroll
  for (int mi = 0; mi < 2; mi++)
#pragma unroll
    for (int ni = 0; ni < 2; ni++) {
      int col = c0 + ni*8;
      *(float2*)(out + (size_t)(r0 + mi*16) * G3 + col)     = make_float2(c[mi][ni][0], c[mi][ni][1]);
      *(float2*)(out + (size_t)(r0 + mi*16 + 8) * G3 + col) = make_float2(c[mi][ni][2], c[mi][ni][3]);
    }
}

// ---------------------------------------------------------------------------
// Stage 2: gates -> hpre (fp32 + bf16 planes), bitonic sort -> sh planes.
// ---------------------------------------------------------------------------
__global__ void __launch_bounds__(256) gatesort_k(Ptrs P, int w, int lmin, int pp) {
  int l = lmin + blockIdx.y, t = w - l;
  int warp = threadIdx.x >> 5, lane = threadIdx.x & 31;
  int b = blockIdx.x * 8 + warp;
  __shared__ float vbuf[8][256];
  float* v = vbuf[warp];
  const float* bi = P.bih + l * G3;
  const float* bh = P.bhh + l * G3;
#pragma unroll
  for (int q = 0; q < 8; q++) {
    int j = lane + (q << 5);
    float gi0 = g_Gi[l][b][j]      + bi[j];
    float gi1 = g_Gi[l][b][j+256]  + bi[j+256];
    float gi2 = g_Gi[l][b][j+512]  + bi[j+512];
    float gh0 = g_Gh[l][b][j]      + bh[j];
    float gh1 = g_Gh[l][b][j+256]  + bh[j+256];
    float gh2 = g_Gh[l][b][j+512]  + bh[j+512];
    float r = 1.f / (1.f + expf(-(gi0 + gh0)));
    float z = 1.f / (1.f + expf(-(gi1 + gh1)));
    float n = tanhf(gi2 + r * gh2);
    float hp = (t == 0) ? P.h0[l * HH + j] : g_h[pp][l][b][j];
    float hv = (1.f - z) * n + z * hp;
    g_hpre[l][b][j] = hv;
    split1(hv, g_hpreh[l][b][j], g_hprel[l][b][j]);
    v[j] = hv;
  }
  __syncwarp();
  for (int k = 2; k <= 256; k <<= 1) {
    for (int jj = k >> 1; jj > 0; jj >>= 1) {
#pragma unroll
      for (int q = 0; q < 8; q++) {
        int idx = lane + (q << 5);
        int ixj = idx ^ jj;
        if (ixj > idx) {
          float a = v[idx], cc = v[ixj];
          bool up = ((idx & k) == 0);
          if ((a > cc) == up) { v[idx] = cc; v[ixj] = a; }
        }
      }
      __syncwarp();
    }
  }
#pragma unroll
  for (int q = 0; q < 8; q++) {
    int j = lane + (q << 5);
    split1(v[j], g_shh[l][b][j], g_shl[l][b][j]);
  }
}

// ---------------------------------------------------------------------------
// Stage 3 (tensor, fused a1+a2+a3): A3 = relu([hpre|sh] @ P^T). grid(32, nA)
// ---------------------------------------------------------------------------
__global__ void __launch_bounds__(256) attn_k(int lmin) {
  __shared__ __align__(16) bf16 sm[2*SMBUF];
  int l = lmin + blockIdx.y;
  int i = blockIdx.x;
  int m0 = (i & 3) << 6, n0 = (i >> 2) << 6;
  float c[2][2][4] = {};
  mma_tileb(&g_hpreh[l][m0][0], &g_hprel[l][m0][0],
            &g_shh[l][m0][0],   &g_shl[l][m0][0], 256,
            &g_Ph[l][n0][0],    &g_Pl[l][n0][0], 512, 512, c, sm);
  int lane = threadIdx.x & 31, wid = threadIdx.x >> 5;
  int wm = wid >> 2, wn = wid & 3;
  int r0 = m0 + wm*32 + (lane >> 2);
  int c0 = n0 + wn*16 + 2*(lane & 3);
#pragma unroll
  for (int mi = 0; mi < 2; mi++)
#pragma unroll
    for (int ni = 0; ni < 2; ni++) {
      int col = c0 + ni*8;
#pragma unroll
      for (int half = 0; half < 2; half++) {
        int row = r0 + mi*16 + half*8;
        float v0 = fmaxf(c[mi][ni][half*2], 0.f);
        float v1 = fmaxf(c[mi][ni][half*2+1], 0.f);
        unsigned hi, lo; split2u(v0, v1, hi, lo);
        *(unsigned*)(&g_A3h[l][row][col]) = hi;
        *(unsigned*)(&g_A3l[l][row][col]) = lo;
      }
    }
}

// ---------------------------------------------------------------------------
// Stage 4 (tensor): a4 = A3 @ W4^T ; h = hpre * sigmoid(a4). grid(16, nA)
// ---------------------------------------------------------------------------
__global__ void __launch_bounds__(256) a4_k(Ptrs P, int w, int lmin, int p) {
  __shared__ __align__(16) bf16 sm[2*SMBUF];
  int l = lmin + blockIdx.y, t = w - l;
  int i = blockIdx.x;
  int m0 = (i & 3) << 6, n0 = (i >> 2) << 6;
  float c[2][2][4] = {};
  mma_tileb(&g_A3h[l][m0][0], &g_A3l[l][m0][0],
            &g_A3h[l][m0][256], &g_A3l[l][m0][256], 512,
            &g_W4h[l][n0][0], &g_W4l[l][n0][0], 512, 512, c, sm);
  int lane = threadIdx.x & 31, wid = threadIdx.x >> 5;
  int wm = wid >> 2, wn = wid & 3;
  int r0 = m0 + wm*32 + (lane >> 2);
  int c0 = n0 + wn*16 + 2*(lane & 3);
#pragma unroll
  for (int mi = 0; mi < 2; mi++)
#pragma unroll
    for (int ni = 0; ni < 2; ni++) {
      int col = c0 + ni*8;
#pragma unroll
      for (int half = 0; half < 2; half++) {
        int row = r0 + mi*16 + half*8;
        float va = c[mi][ni][half*2], vb = c[mi][ni][half*2+1];
        float2 hp = *(float2*)(&g_hpre[l][row][col]);
        float h0v = hp.x * (1.f / (1.f + expf(-va)));
        float h1v = hp.y * (1.f / (1.f + expf(-vb)));
        *(float2*)(&g_h[p][l][row][col]) = make_float2(h0v, h1v);
        unsigned hi, lo; split2u(h0v, h1v, hi, lo);
        *(unsigned*)(&g_hbh[p][l][row][col]) = hi;
        *(unsigned*)(&g_hbl[p][l][row][col]) = lo;
        if (l == NLY - 1)
          *(float2*)(P.out + (size_t)row * 32768 + (size_t)t * 256 + col) = make_float2(h0v, h1v);
      }
    }
}

// ---------------------------------------------------------------------------
__global__ void seqdec_kernel(Ptrs P) {
  int idx = blockIdx.x * blockDim.x + threadIdx.x;
  int b = idx >> 7, s = idx & 127;
  const float* e = P.out + (size_t)b * 32768 + (size_t)s * 256;
  float a1[8][4], a2[8][4], a3[8][4];
#pragma unroll
  for (int g = 0; g < 8; g++)
#pragma unroll
    for (int o = 0; o < 4; o++) {
      float sum = P.sdb1[o];
#pragma unroll
      for (int m = 0; m < 32; m++) sum += e[g*32+m] * P.sdW1[o*32+m];
      a1[g][o] = sum;
    }
#pragma unroll
  for (int i = 0; i < 8; i++)
#pragma unroll
    for (int o = 0; o < 4; o++) {
      float sum = P.sdb2[o];
#pragma unroll
      for (int j = 0; j < 4; j++) {
        int f = i*4 + j;
        sum += a1[f & 7][f >> 3] * P.sdW2[o*4+j];
      }
      a2[i][o] = sum;
    }
#pragma unroll
  for (int i = 0; i < 8; i++)
#pragma unroll
    for (int o = 0; o < 4; o++) {
      float sum = P.sdb3[o];
#pragma unroll
      for (int j = 0; j < 4; j++) {
        int f = i*4 + j;
        sum += a2[f & 7][f >> 3] * P.sdW3[o*4+j];
      }
      a3[i][o] = sum;
    }
#pragma unroll
  for (int o = 0; o < 4; o++)
#pragma unroll
    for (int wv = 0; wv < 8; wv++) {
      float sum = P.sdb4[wv];
#pragma unroll
      for (int g = 0; g < 8; g++) {
        int f = o*8 + g;
        sum += a3[f >> 2][f & 3] * P.sdW4[wv*8+g];
      }
      P.out[YSEQ_OFF + (size_t)b * 4096 + (size_t)(s*8 + wv) * 4 + o] = sum;
    }
}

// ---------------------------------------------------------------------------
__global__ void onedec_kernel(Ptrs P) {
  int b = blockIdx.x;
  __shared__ float acc[10][4];
  int tid = threadIdx.x;
  if (tid < 10) {
    int s = 118 + tid;
    const float* e = P.out + (size_t)b * 32768 + (size_t)s * 256;
    float o1[8][4], o2[8][4], o3[8][4];
#pragma unroll
    for (int g = 0; g < 8; g++)
#pragma unroll
      for (int o = 0; o < 4; o++) {
        float sum = P.odb1[o];
#pragma unroll
        for (int m = 0; m < 32; m++) sum += e[g*32+m] * P.odW1[o*32+m];
        o1[g][o] = sum;
      }
#pragma unroll
    for (int i = 0; i < 8; i++)
#pragma unroll
      for (int o = 0; o < 4; o++) {
        float sum = P.odb2[o];
#pragma unroll
        for (int j = 0; j < 4; j++) {
          int f = i*4 + j;
          sum += o1[f & 7][f >> 3] * P.odW2[o*4+j];
        }
        o2[i][o] = sum;
      }
#pragma unroll
    for (int i = 0; i < 8; i++)
#pragma unroll
      for (int o = 0; o < 4; o++) {
        float sum = P.odb3[o];
#pragma unroll
        for (int j = 0; j < 4; j++) {
          int f = i*4 + j;
          sum += o2[f & 7][f >> 3] * P.odW3[o*4+j];
        }
        o3[i][o] = fmaxf(sum, 0.f);
      }
#pragma unroll
    for (int c = 0; c < 4; c++) {
      float sum = P.odb4[c];
#pragma unroll
      for (int f = 0; f < 32; f++) sum += o3[f >> 2][f & 3] * P.odW4[c*32+f];
      acc[tid][c] = 1.f / (1.f + expf(-sum));
    }
  }
  __syncthreads();
  if (tid < 4) {
    float s = 0.f;
#pragma unroll
    for (int i = 0; i < 10; i++) s += acc[i][tid];
    P.out[YONE_OFF + (size_t)b * 4 + tid] = s * 0.1f;
  }
}

// ---------------------------------------------------------------------------
extern "C" void kernel_launch(void* const* d_in, const int* in_sizes, int n_in,
                              void* d_out, int out_size) {
  (void)in_sizes; (void)n_in; (void)out_size;
  Ptrs P;
  P.x    = (const float*)d_in[0];
  P.Wih0 = (const float*)d_in[1];
  P.Wih  = (const float*)d_in[2];
  P.Whh  = (const float*)d_in[3];
  P.bih  = (const float*)d_in[4];
  P.bhh  = (const float*)d_in[5];
  P.h0   = (const float*)d_in[6];
  P.aW1  = (const float*)d_in[7];
  P.aW2  = (const float*)d_in[8];
  P.aW3  = (const float*)d_in[9];
  P.aW4  = (const float*)d_in[10];
  P.sdW1 = (const float*)d_in[11];
  P.sdb1 = (const float*)d_in[12];
  P.sdW2 = (const float*)d_in[13];
  P.sdb2 = (const float*)d_in[14];
  P.sdW3 = (const float*)d_in[15];
  P.sdb3 = (const float*)d_in[16];
  P.sdW4 = (const float*)d_in[17];
  P.sdb4 = (const float*)d_in[18];
  P.odW1 = (const float*)d_in[19];
  P.odb1 = (const float*)d_in[20];
  P.odW2 = (const float*)d_in[21];
  P.odb2 = (const float*)d_in[22];
  P.odW3 = (const float*)d_in[23];
  P.odb3 = (const float*)d_in[24];
  P.odW4 = (const float*)d_in[25];
  P.odb4 = (const float*)d_in[26];
  P.out  = (float*)d_out;

  // one-time: fold SortAttn into dense P; split all static operands to bf16 planes
  prep_zero<<<6144, 256>>>();
  prep_scatter<<<1536, 256>>>(P);
  prep_w1t<<<1536, 256>>>(P);
  prep_md<<<dim3(64, NLY), 256>>>();
  prep_p<<<dim3(64, NLY), 256>>>();
  sp_x<<<16384, 256>>>(P);
  sp_w0<<<384, 256>>>(P);
  sp_wih<<<3840, 256>>>(P);
  sp_whh<<<4608, 256>>>(P);
  sp_w4<<<3072, 256>>>(P);
  sp_h0<<<6, 256>>>(P);
  sp_P<<<6144, 256>>>();

  for (int w = 0; w < SS + NLY - 1; w++) {
    int lmin = w - (SS - 1); if (lmin < 0) lmin = 0;
    int lmax = (w < NLY - 1) ? w : NLY - 1;
    int nA = lmax - lmin + 1;
    int pp = (w + 1) & 1;
    int p  = w & 1;
    stage1_k<<<dim3(96, nA), 256>>>(P, w, lmin, pp);
    gatesort_k<<<dim3(32, nA), 256>>>(P, w, lmin, pp);
    attn_k<<<dim3(32, nA), 256>>>(lmin);
    a4_k<<<dim3(16, nA), 256>>>(P, w, lmin, p);
  }

  seqdec_kernel<<<128, 256>>>(P);
  onedec_kernel<<<256, 32>>>(P);
}